// round 1
// baseline (speedup 1.0000x reference)
#include <cuda_runtime.h>
#include <cstdint>

#define N_NODES 50000
#define N_EDGES 640000
#define D 128

// ---------------- device scratch (no allocations allowed) ----------------
__device__ int   g_is64;
__device__ int   g_count[N_NODES];
__device__ int   g_offsets[N_NODES + 1];
__device__ int   g_cursor[N_NODES];
__device__ int   g_src_sorted[N_EDGES];
__device__ float g_w_sorted[N_EDGES];

// Read an edge index that may be stored as int32 or int64.
__device__ __forceinline__ int edge_idx(const void* p, int i, int is64) {
    if (is64) return (int)__ldg(((const long long*)p) + i);
    return __ldg(((const int*)p) + i);
}

// ---------------- dtype detection (int32 vs int64 indices) ----------------
__global__ void detect_kernel(const void* src, const void* dst) {
    const long long* s = (const long long*)src;
    const long long* d = (const long long*)dst;
    bool ok = true;
    for (int i = 0; i < 8; i++) {
        long long a = s[i], b = d[i];
        if (a < 0 || a >= N_NODES || b < 0 || b >= N_NODES) { ok = false; break; }
    }
    g_is64 = ok ? 1 : 0;
}

// ---------------- CSR build: count, scan, scatter ----------------
__global__ void zero_count_kernel() {
    int i = blockIdx.x * blockDim.x + threadIdx.x;
    if (i < N_NODES) g_count[i] = 0;
}

__global__ void count_kernel(const void* dst) {
    int e = blockIdx.x * blockDim.x + threadIdx.x;
    if (e >= N_EDGES) return;
    int is64 = g_is64;
    atomicAdd(&g_count[edge_idx(dst, e, is64)], 1);
}

// Single-block exclusive scan over 50000 counts (1024 threads, 49 items each).
__global__ void scan_kernel() {
    __shared__ int partials[1024];
    const int CH = (N_NODES + 1023) / 1024;  // 49
    int t = threadIdx.x;
    int start = t * CH;
    int sum = 0;
    for (int i = 0; i < CH; i++) {
        int idx = start + i;
        if (idx < N_NODES) sum += g_count[idx];
    }
    partials[t] = sum;
    __syncthreads();
    // Hillis-Steele inclusive scan
    for (int off = 1; off < 1024; off <<= 1) {
        int v = (t >= off) ? partials[t - off] : 0;
        __syncthreads();
        partials[t] += v;
        __syncthreads();
    }
    int run = (t == 0) ? 0 : partials[t - 1];  // exclusive prefix of this chunk
    for (int i = 0; i < CH; i++) {
        int idx = start + i;
        if (idx < N_NODES) {
            g_offsets[idx] = run;
            g_cursor[idx]  = run;
            run += g_count[idx];
        }
    }
    if (t == 0) g_offsets[N_NODES] = N_EDGES;
}

__global__ void scatter_kernel(const void* src, const void* dst, const float* __restrict__ w) {
    int e = blockIdx.x * blockDim.x + threadIdx.x;
    if (e >= N_EDGES) return;
    int is64 = g_is64;
    int d = edge_idx(dst, e, is64);
    int pos = atomicAdd(&g_cursor[d], 1);
    g_src_sorted[pos] = edge_idx(src, e, is64);
    g_w_sorted[pos]   = __ldg(w + e);
}

// ---------------- per-node aggregation: one warp per node ----------------
__global__ void aggregate_kernel(const float* __restrict__ nfeat, float* __restrict__ hn) {
    int gwarp = (blockIdx.x * blockDim.x + threadIdx.x) >> 5;
    int lane  = threadIdx.x & 31;
    if (gwarp >= N_NODES) return;
    int beg = g_offsets[gwarp];
    int end = g_offsets[gwarp + 1];
    float4 acc = make_float4(0.f, 0.f, 0.f, 0.f);
    for (int e = beg; e < end; e++) {
        int   s  = g_src_sorted[e];
        float wt = g_w_sorted[e];
        float4 v = __ldg(((const float4*)(nfeat + (size_t)s * D)) + lane);
        acc.x += wt * v.x;
        acc.y += wt * v.y;
        acc.z += wt * v.z;
        acc.w += wt * v.w;
    }
    ((float4*)(hn + (size_t)gwarp * D))[lane] = acc;
}

// ---------------- fused bi-interaction: out = lrelu((h+hn)W1^T) + lrelu((h*hn)W2^T) ----------------
__device__ __forceinline__ float lrelu(float x) { return x > 0.f ? x : 0.01f * x; }

#define WPAD 132                 // 128 + 4 pad: 16B-aligned rows, spread banks
#define TILE_ROWS 64

__global__ void fused_gemm_kernel(const float* __restrict__ nfeat,
                                  const float* __restrict__ W1,
                                  const float* __restrict__ W2,
                                  const float* __restrict__ hn,
                                  float* __restrict__ out) {
    extern __shared__ float smem[];
    float* Wt1 = smem;                    // [128][WPAD]  k-major: Wt1[k][c] = W1[c][k]
    float* Wt2 = Wt1 + 128 * WPAD;
    float* As  = Wt2 + 128 * WPAD;        // [64][128]
    float* Ms  = As + TILE_ROWS * 128;    // [64][128]

    int tid = threadIdx.x;

    // load + transpose weights (once per block)
    for (int idx = tid; idx < 128 * 128; idx += 256) {
        int c = idx >> 7;
        int k = idx & 127;
        Wt1[k * WPAD + c] = W1[idx];
        Wt2[k * WPAD + c] = W2[idx];
    }

    int tx = tid & 15;          // 16 col-groups of 8
    int ty = tid >> 4;          // 16 row-groups of 4
    int r0 = ty * 4;
    int c0 = tx * 8;

    const int n_tiles = (N_NODES + TILE_ROWS - 1) / TILE_ROWS;
    for (int tile = blockIdx.x; tile < n_tiles; tile += gridDim.x) {
        int n0 = tile * TILE_ROWS;
        __syncthreads();  // also covers first-iter weight transpose

        // stage A = h + hn, M = h * hn
        for (int idx = tid; idx < TILE_ROWS * 32; idx += 256) {
            int r  = idx >> 5;
            int c4 = idx & 31;
            int g  = n0 + r;
            float4 hv = make_float4(0.f, 0.f, 0.f, 0.f);
            float4 nv = hv;
            if (g < N_NODES) {
                hv = __ldg(((const float4*)(nfeat + (size_t)g * D)) + c4);
                nv = __ldg(((const float4*)(hn   + (size_t)g * D)) + c4);
            }
            float4 av, mv;
            av.x = hv.x + nv.x; av.y = hv.y + nv.y; av.z = hv.z + nv.z; av.w = hv.w + nv.w;
            mv.x = hv.x * nv.x; mv.y = hv.y * nv.y; mv.z = hv.z * nv.z; mv.w = hv.w * nv.w;
            ((float4*)As)[idx] = av;
            ((float4*)Ms)[idx] = mv;
        }
        __syncthreads();

        float acc1[4][8];
        float acc2[4][8];
        #pragma unroll
        for (int i = 0; i < 4; i++)
            #pragma unroll
            for (int j = 0; j < 8; j++) { acc1[i][j] = 0.f; acc2[i][j] = 0.f; }

        const float* Arow = As + r0 * 128;
        const float* Mrow = Ms + r0 * 128;

        #pragma unroll 4
        for (int k = 0; k < 128; k++) {
            float a[4], m[4];
            #pragma unroll
            for (int i = 0; i < 4; i++) {
                a[i] = Arow[i * 128 + k];
                m[i] = Mrow[i * 128 + k];
            }
            float4 w1lo = *(const float4*)(Wt1 + k * WPAD + c0);
            float4 w1hi = *(const float4*)(Wt1 + k * WPAD + c0 + 4);
            float4 w2lo = *(const float4*)(Wt2 + k * WPAD + c0);
            float4 w2hi = *(const float4*)(Wt2 + k * WPAD + c0 + 4);
            float w1[8] = {w1lo.x, w1lo.y, w1lo.z, w1lo.w, w1hi.x, w1hi.y, w1hi.z, w1hi.w};
            float w2[8] = {w2lo.x, w2lo.y, w2lo.z, w2lo.w, w2hi.x, w2hi.y, w2hi.z, w2hi.w};
            #pragma unroll
            for (int i = 0; i < 4; i++)
                #pragma unroll
                for (int j = 0; j < 8; j++) {
                    acc1[i][j] += a[i] * w1[j];
                    acc2[i][j] += m[i] * w2[j];
                }
        }

        #pragma unroll
        for (int i = 0; i < 4; i++) {
            int g = n0 + r0 + i;
            if (g < N_NODES) {
                float4 o0, o1;
                o0.x = lrelu(acc1[i][0]) + lrelu(acc2[i][0]);
                o0.y = lrelu(acc1[i][1]) + lrelu(acc2[i][1]);
                o0.z = lrelu(acc1[i][2]) + lrelu(acc2[i][2]);
                o0.w = lrelu(acc1[i][3]) + lrelu(acc2[i][3]);
                o1.x = lrelu(acc1[i][4]) + lrelu(acc2[i][4]);
                o1.y = lrelu(acc1[i][5]) + lrelu(acc2[i][5]);
                o1.z = lrelu(acc1[i][6]) + lrelu(acc2[i][6]);
                o1.w = lrelu(acc1[i][7]) + lrelu(acc2[i][7]);
                float* op = out + (size_t)g * D + c0;
                *(float4*)op       = o0;
                *(float4*)(op + 4) = o1;
            }
        }
    }
}

// ---------------- launch ----------------
extern "C" void kernel_launch(void* const* d_in, const int* in_sizes, int n_in,
                              void* d_out, int out_size) {
    const float* nfeat = (const float*)d_in[0];
    const float* w     = (const float*)d_in[1];
    const float* W1    = (const float*)d_in[2];
    const float* W2    = (const float*)d_in[3];
    const void*  src   = d_in[4];
    const void*  dst   = d_in[5];

    float* outbuf = (float*)d_out;
    float* hn     = outbuf;                           // first N*D floats: h_neighbor
    float* out2   = outbuf + (size_t)N_NODES * D;     // second N*D floats: out

    detect_kernel<<<1, 1>>>(src, dst);
    zero_count_kernel<<<(N_NODES + 255) / 256, 256>>>();
    count_kernel<<<(N_EDGES + 255) / 256, 256>>>(dst);
    scan_kernel<<<1, 1024>>>();
    scatter_kernel<<<(N_EDGES + 255) / 256, 256>>>(src, dst, w);
    aggregate_kernel<<<(N_NODES * 32 + 255) / 256, 256>>>(nfeat, hn);

    size_t smem_bytes = (size_t)(2 * 128 * WPAD + 2 * TILE_ROWS * 128) * sizeof(float);
    cudaFuncSetAttribute(fused_gemm_kernel,
                         cudaFuncAttributeMaxDynamicSharedMemorySize, (int)smem_bytes);
    fused_gemm_kernel<<<148, 256, smem_bytes>>>(nfeat, W1, W2, hn, out2);
}

// round 2
// speedup vs baseline: 1.3853x; 1.3853x over previous
#include <cuda_runtime.h>
#include <cstdint>

#define N_NODES 50000
#define N_EDGES 640000
#define D 128

#define SCAN_TILE 1024
#define SCAN_NBLK ((N_NODES + SCAN_TILE - 1) / SCAN_TILE)   // 49

// ---------------- device scratch (no allocations allowed) ----------------
__device__ int   g_is64;
__device__ int   g_count[N_NODES];
__device__ int   g_offsets[N_NODES + 1];
__device__ int   g_cursor[N_NODES];
__device__ int   g_blocksums[SCAN_NBLK];
__device__ int   g_blockoffs[SCAN_NBLK];
__device__ int   g_src_sorted[N_EDGES];
__device__ float g_w_sorted[N_EDGES];

// Read an edge index that may be stored as int32 or int64.
__device__ __forceinline__ int edge_idx(const void* p, int i, int is64) {
    if (is64) return (int)__ldg(((const long long*)p) + i);
    return __ldg(((const int*)p) + i);
}

// ---------------- dtype detection + zero counts (fused) ----------------
__global__ void zero_detect_kernel(const void* src, const void* dst) {
    int i = blockIdx.x * blockDim.x + threadIdx.x;
    if (i < N_NODES) g_count[i] = 0;
    if (i == 0) {
        const long long* s = (const long long*)src;
        const long long* d = (const long long*)dst;
        bool ok = true;
        for (int j = 0; j < 8; j++) {
            long long a = s[j], b = d[j];
            if (a < 0 || a >= N_NODES || b < 0 || b >= N_NODES) { ok = false; break; }
        }
        g_is64 = ok ? 1 : 0;
    }
}

__global__ void count_kernel(const void* dst) {
    int e = blockIdx.x * blockDim.x + threadIdx.x;
    if (e >= N_EDGES) return;
    int is64 = g_is64;
    atomicAdd(&g_count[edge_idx(dst, e, is64)], 1);
}

// ---------------- multi-block exclusive scan over g_count ----------------
// Pass 1: per-block tile reduction (tile = 1024 counts, 256 threads x 4 each)
__global__ void scan_pass1() {
    __shared__ int warpsums[8];
    int t = threadIdx.x;
    int base = blockIdx.x * SCAN_TILE + t * 4;
    int s = 0;
    #pragma unroll
    for (int i = 0; i < 4; i++) {
        int idx = base + i;
        if (idx < N_NODES) s += g_count[idx];
    }
    // warp reduce
    #pragma unroll
    for (int o = 16; o > 0; o >>= 1) s += __shfl_down_sync(0xFFFFFFFF, s, o);
    if ((t & 31) == 0) warpsums[t >> 5] = s;
    __syncthreads();
    if (t == 0) {
        int tot = 0;
        #pragma unroll
        for (int wv = 0; wv < 8; wv++) tot += warpsums[wv];
        g_blocksums[blockIdx.x] = tot;
    }
}

// Pass 2: single small block scans the 49 block sums (exclusive)
__global__ void scan_pass2() {
    if (threadIdx.x == 0) {
        int run = 0;
        for (int b = 0; b < SCAN_NBLK; b++) {
            g_blockoffs[b] = run;
            run += g_blocksums[b];
        }
        g_offsets[N_NODES] = N_EDGES;
    }
}

// Pass 3: per-block in-tile exclusive scan + block offset; write offsets+cursor
__global__ void scan_pass3() {
    __shared__ int warpsums[8];
    int t    = threadIdx.x;
    int lane = t & 31;
    int wrp  = t >> 5;
    int base = blockIdx.x * SCAN_TILE + t * 4;

    int c[4];
    int lsum = 0;
    #pragma unroll
    for (int i = 0; i < 4; i++) {
        int idx = base + i;
        c[i] = (idx < N_NODES) ? g_count[idx] : 0;
        lsum += c[i];
    }
    // warp inclusive scan of lsum
    int incl = lsum;
    #pragma unroll
    for (int o = 1; o < 32; o <<= 1) {
        int v = __shfl_up_sync(0xFFFFFFFF, incl, o);
        if (lane >= o) incl += v;
    }
    if (lane == 31) warpsums[wrp] = incl;
    __syncthreads();
    int wbase = 0;
    #pragma unroll
    for (int wv = 0; wv < 8; wv++) {
        int v = warpsums[wv];
        if (wv < wrp) wbase += v;
    }
    int run = g_blockoffs[blockIdx.x] + wbase + (incl - lsum);
    #pragma unroll
    for (int i = 0; i < 4; i++) {
        int idx = base + i;
        if (idx < N_NODES) {
            g_offsets[idx] = run;
            g_cursor[idx]  = run;
            run += c[i];
        }
    }
}

__global__ void scatter_kernel(const void* src, const void* dst, const float* __restrict__ w) {
    int e = blockIdx.x * blockDim.x + threadIdx.x;
    if (e >= N_EDGES) return;
    int is64 = g_is64;
    int d = edge_idx(dst, e, is64);
    int pos = atomicAdd(&g_cursor[d], 1);
    g_src_sorted[pos] = edge_idx(src, e, is64);
    g_w_sorted[pos]   = __ldg(w + e);
}

// ---------------- per-node aggregation: one warp per node ----------------
__global__ void aggregate_kernel(const float* __restrict__ nfeat, float* __restrict__ hn) {
    int gwarp = (blockIdx.x * blockDim.x + threadIdx.x) >> 5;
    int lane  = threadIdx.x & 31;
    if (gwarp >= N_NODES) return;
    int beg = g_offsets[gwarp];
    int end = g_offsets[gwarp + 1];
    float4 acc = make_float4(0.f, 0.f, 0.f, 0.f);
    for (int e = beg; e < end; e++) {
        int   s  = g_src_sorted[e];
        float wt = g_w_sorted[e];
        float4 v = __ldg(((const float4*)(nfeat + (size_t)s * D)) + lane);
        acc.x += wt * v.x;
        acc.y += wt * v.y;
        acc.z += wt * v.z;
        acc.w += wt * v.w;
    }
    ((float4*)(hn + (size_t)gwarp * D))[lane] = acc;
}

// ---------------- fused bi-interaction: out = lrelu((h+hn)W1^T) + lrelu((h*hn)W2^T) ----------------
__device__ __forceinline__ float lrelu(float x) { return x > 0.f ? x : 0.01f * x; }

#define WPAD 132                 // 128 + 4 pad: 16B-aligned rows, spread banks
#define TILE_ROWS 64

__global__ void fused_gemm_kernel(const float* __restrict__ nfeat,
                                  const float* __restrict__ W1,
                                  const float* __restrict__ W2,
                                  const float* __restrict__ hn,
                                  float* __restrict__ out) {
    extern __shared__ float smem[];
    float* Wt1 = smem;                    // [128][WPAD]  k-major: Wt1[k][c] = W1[c][k]
    float* Wt2 = Wt1 + 128 * WPAD;
    float* As  = Wt2 + 128 * WPAD;        // [64][128]
    float* Ms  = As + TILE_ROWS * 128;    // [64][128]

    int tid = threadIdx.x;

    // load + transpose weights (once per block)
    for (int idx = tid; idx < 128 * 128; idx += 256) {
        int c = idx >> 7;
        int k = idx & 127;
        Wt1[k * WPAD + c] = W1[idx];
        Wt2[k * WPAD + c] = W2[idx];
    }

    int tx = tid & 15;          // 16 col-groups of 8
    int ty = tid >> 4;          // 16 row-groups of 4
    int r0 = ty * 4;
    int c0 = tx * 8;

    const int n_tiles = (N_NODES + TILE_ROWS - 1) / TILE_ROWS;
    for (int tile = blockIdx.x; tile < n_tiles; tile += gridDim.x) {
        int n0 = tile * TILE_ROWS;
        __syncthreads();  // also covers first-iter weight transpose

        // stage A = h + hn, M = h * hn
        for (int idx = tid; idx < TILE_ROWS * 32; idx += 256) {
            int r  = idx >> 5;
            int c4 = idx & 31;
            int g  = n0 + r;
            float4 hv = make_float4(0.f, 0.f, 0.f, 0.f);
            float4 nv = hv;
            if (g < N_NODES) {
                hv = __ldg(((const float4*)(nfeat + (size_t)g * D)) + c4);
                nv = __ldg(((const float4*)(hn   + (size_t)g * D)) + c4);
            }
            float4 av, mv;
            av.x = hv.x + nv.x; av.y = hv.y + nv.y; av.z = hv.z + nv.z; av.w = hv.w + nv.w;
            mv.x = hv.x * nv.x; mv.y = hv.y * nv.y; mv.z = hv.z * nv.z; mv.w = hv.w * nv.w;
            ((float4*)As)[idx] = av;
            ((float4*)Ms)[idx] = mv;
        }
        __syncthreads();

        float acc1[4][8];
        float acc2[4][8];
        #pragma unroll
        for (int i = 0; i < 4; i++)
            #pragma unroll
            for (int j = 0; j < 8; j++) { acc1[i][j] = 0.f; acc2[i][j] = 0.f; }

        const float* Arow = As + r0 * 128;
        const float* Mrow = Ms + r0 * 128;

        #pragma unroll 4
        for (int k = 0; k < 128; k++) {
            float a[4], m[4];
            #pragma unroll
            for (int i = 0; i < 4; i++) {
                a[i] = Arow[i * 128 + k];
                m[i] = Mrow[i * 128 + k];
            }
            float4 w1lo = *(const float4*)(Wt1 + k * WPAD + c0);
            float4 w1hi = *(const float4*)(Wt1 + k * WPAD + c0 + 4);
            float4 w2lo = *(const float4*)(Wt2 + k * WPAD + c0);
            float4 w2hi = *(const float4*)(Wt2 + k * WPAD + c0 + 4);
            float w1[8] = {w1lo.x, w1lo.y, w1lo.z, w1lo.w, w1hi.x, w1hi.y, w1hi.z, w1hi.w};
            float w2[8] = {w2lo.x, w2lo.y, w2lo.z, w2lo.w, w2hi.x, w2hi.y, w2hi.z, w2hi.w};
            #pragma unroll
            for (int i = 0; i < 4; i++)
                #pragma unroll
                for (int j = 0; j < 8; j++) {
                    acc1[i][j] += a[i] * w1[j];
                    acc2[i][j] += m[i] * w2[j];
                }
        }

        #pragma unroll
        for (int i = 0; i < 4; i++) {
            int g = n0 + r0 + i;
            if (g < N_NODES) {
                float4 o0, o1;
                o0.x = lrelu(acc1[i][0]) + lrelu(acc2[i][0]);
                o0.y = lrelu(acc1[i][1]) + lrelu(acc2[i][1]);
                o0.z = lrelu(acc1[i][2]) + lrelu(acc2[i][2]);
                o0.w = lrelu(acc1[i][3]) + lrelu(acc2[i][3]);
                o1.x = lrelu(acc1[i][4]) + lrelu(acc2[i][4]);
                o1.y = lrelu(acc1[i][5]) + lrelu(acc2[i][5]);
                o1.z = lrelu(acc1[i][6]) + lrelu(acc2[i][6]);
                o1.w = lrelu(acc1[i][7]) + lrelu(acc2[i][7]);
                float* op = out + (size_t)g * D + c0;
                *(float4*)op       = o0;
                *(float4*)(op + 4) = o1;
            }
        }
    }
}

// ---------------- launch ----------------
extern "C" void kernel_launch(void* const* d_in, const int* in_sizes, int n_in,
                              void* d_out, int out_size) {
    const float* nfeat = (const float*)d_in[0];
    const float* w     = (const float*)d_in[1];
    const float* W1    = (const float*)d_in[2];
    const float* W2    = (const float*)d_in[3];
    const void*  src   = d_in[4];
    const void*  dst   = d_in[5];

    float* outbuf = (float*)d_out;
    float* hn     = outbuf;                           // first N*D floats: h_neighbor
    float* out2   = outbuf + (size_t)N_NODES * D;     // second N*D floats: out

    zero_detect_kernel<<<(N_NODES + 255) / 256, 256>>>(src, dst);
    count_kernel<<<(N_EDGES + 255) / 256, 256>>>(dst);
    scan_pass1<<<SCAN_NBLK, 256>>>();
    scan_pass2<<<1, 32>>>();
    scan_pass3<<<SCAN_NBLK, 256>>>();
    scatter_kernel<<<(N_EDGES + 255) / 256, 256>>>(src, dst, w);
    aggregate_kernel<<<(N_NODES * 32 + 255) / 256, 256>>>(nfeat, hn);

    size_t smem_bytes = (size_t)(2 * 128 * WPAD + 2 * TILE_ROWS * 128) * sizeof(float);
    cudaFuncSetAttribute(fused_gemm_kernel,
                         cudaFuncAttributeMaxDynamicSharedMemorySize, (int)smem_bytes);
    fused_gemm_kernel<<<148, 256, smem_bytes>>>(nfeat, W1, W2, hn, out2);
}

// round 3
// speedup vs baseline: 1.8309x; 1.3216x over previous
#include <cuda_runtime.h>
#include <cstdint>

#define N_NODES 50000
#define N_EDGES 640000
#define D 128

#define SCAN_TILE 1024
#define SCAN_NBLK ((N_NODES + SCAN_TILE - 1) / SCAN_TILE)   // 49

// ---------------- device scratch (no allocations allowed) ----------------
__device__ int                g_is64;
__device__ int                g_count[N_NODES];
__device__ int                g_offsets[N_NODES + 1];
__device__ int                g_cursor[N_NODES];
__device__ unsigned int       g_scanstate[SCAN_NBLK];   // bit31 = ready, low bits = block sum
__device__ unsigned long long g_edge_sorted[N_EDGES];   // (w_bits<<32) | src

// Read an edge index that may be stored as int32 or int64.
__device__ __forceinline__ int edge_idx(const void* p, int i, int is64) {
    if (is64) return (int)__ldg(((const long long*)p) + i);
    return __ldg(((const int*)p) + i);
}

// ---------------- init: zero counts + scan state, detect index dtype ----------------
__global__ void zero_detect_kernel(const void* src, const void* dst) {
    int i = blockIdx.x * blockDim.x + threadIdx.x;
    if (i < N_NODES) g_count[i] = 0;
    if (i < SCAN_NBLK) g_scanstate[i] = 0u;
    if (i == 0) {
        g_offsets[N_NODES] = N_EDGES;
        const long long* s = (const long long*)src;
        const long long* d = (const long long*)dst;
        bool ok = true;
        for (int j = 0; j < 8; j++) {
            long long a = s[j], b = d[j];
            if (a < 0 || a >= N_NODES || b < 0 || b >= N_NODES) { ok = false; break; }
        }
        g_is64 = ok ? 1 : 0;
    }
}

__global__ void count_kernel(const void* dst) {
    int e = blockIdx.x * blockDim.x + threadIdx.x;
    if (e >= N_EDGES) return;
    int is64 = g_is64;
    atomicAdd(&g_count[edge_idx(dst, e, is64)], 1);
}

// ---------------- single-pass exclusive scan with decoupled lookback ----------------
// 49 blocks, all concurrently resident (148 SMs) -> no starvation.
__global__ void scan_lookback_kernel() {
    __shared__ int warpsums[8];
    __shared__ int blockexcl;
    int t    = threadIdx.x;
    int lane = t & 31;
    int wrp  = t >> 5;
    int b    = blockIdx.x;
    int base = b * SCAN_TILE + t * 4;

    int c[4];
    int lsum = 0;
    #pragma unroll
    for (int i = 0; i < 4; i++) {
        int idx = base + i;
        c[i] = (idx < N_NODES) ? g_count[idx] : 0;
        lsum += c[i];
    }
    // warp inclusive scan of lsum
    int incl = lsum;
    #pragma unroll
    for (int o = 1; o < 32; o <<= 1) {
        int v = __shfl_up_sync(0xFFFFFFFF, incl, o);
        if (lane >= o) incl += v;
    }
    if (lane == 31) warpsums[wrp] = incl;
    __syncthreads();

    // block total + publish
    if (t == 0) {
        int tot = 0;
        #pragma unroll
        for (int wv = 0; wv < 8; wv++) tot += warpsums[wv];
        atomicExch(&g_scanstate[b], 0x80000000u | (unsigned)tot);
    }

    // lookback: warp 0 polls all predecessors in parallel
    if (wrp == 0) {
        int psum = 0;
        for (int p = lane; p < b; p += 32) {
            unsigned v;
            do { v = atomicOr(&g_scanstate[p], 0u); } while (!(v & 0x80000000u));
            psum += (int)(v & 0x7FFFFFFFu);
        }
        #pragma unroll
        for (int o = 16; o > 0; o >>= 1) psum += __shfl_down_sync(0xFFFFFFFF, psum, o);
        if (lane == 0) blockexcl = psum;
    }
    __syncthreads();

    int wbase = 0;
    #pragma unroll
    for (int wv = 0; wv < 8; wv++) {
        int v = warpsums[wv];
        if (wv < wrp) wbase += v;
    }
    int run = blockexcl + wbase + (incl - lsum);
    #pragma unroll
    for (int i = 0; i < 4; i++) {
        int idx = base + i;
        if (idx < N_NODES) {
            g_offsets[idx] = run;
            g_cursor[idx]  = run;
            run += c[i];
        }
    }
}

__global__ void scatter_kernel(const void* src, const void* dst, const float* __restrict__ w) {
    int e = blockIdx.x * blockDim.x + threadIdx.x;
    if (e >= N_EDGES) return;
    int is64 = g_is64;
    int d = edge_idx(dst, e, is64);
    int s = edge_idx(src, e, is64);
    float wv = __ldg(w + e);
    int pos = atomicAdd(&g_cursor[d], 1);
    g_edge_sorted[pos] = ((unsigned long long)__float_as_uint(wv) << 32) | (unsigned)s;
}

// ---------------- per-node aggregation: one warp per node ----------------
__global__ void aggregate_kernel(const float* __restrict__ nfeat, float* __restrict__ hn) {
    int gwarp = (blockIdx.x * blockDim.x + threadIdx.x) >> 5;
    int lane  = threadIdx.x & 31;
    if (gwarp >= N_NODES) return;
    int beg = g_offsets[gwarp];
    int end = g_offsets[gwarp + 1];
    float4 acc = make_float4(0.f, 0.f, 0.f, 0.f);
    int e = beg;
    // unroll-2 for MLP
    for (; e + 1 < end; e += 2) {
        unsigned long long p0 = __ldg(&g_edge_sorted[e]);
        unsigned long long p1 = __ldg(&g_edge_sorted[e + 1]);
        int   s0 = (int)(p0 & 0xFFFFFFFFu);
        int   s1 = (int)(p1 & 0xFFFFFFFFu);
        float w0 = __uint_as_float((unsigned)(p0 >> 32));
        float w1 = __uint_as_float((unsigned)(p1 >> 32));
        float4 v0 = __ldg(((const float4*)(nfeat + (size_t)s0 * D)) + lane);
        float4 v1 = __ldg(((const float4*)(nfeat + (size_t)s1 * D)) + lane);
        acc.x += w0 * v0.x; acc.y += w0 * v0.y; acc.z += w0 * v0.z; acc.w += w0 * v0.w;
        acc.x += w1 * v1.x; acc.y += w1 * v1.y; acc.z += w1 * v1.z; acc.w += w1 * v1.w;
    }
    if (e < end) {
        unsigned long long p0 = __ldg(&g_edge_sorted[e]);
        int   s0 = (int)(p0 & 0xFFFFFFFFu);
        float w0 = __uint_as_float((unsigned)(p0 >> 32));
        float4 v0 = __ldg(((const float4*)(nfeat + (size_t)s0 * D)) + lane);
        acc.x += w0 * v0.x; acc.y += w0 * v0.y; acc.z += w0 * v0.z; acc.w += w0 * v0.w;
    }
    ((float4*)(hn + (size_t)gwarp * D))[lane] = acc;
}

// ---------------- fused bi-interaction GEMM with packed f32x2 FMA ----------------
// out = lrelu((h+hn) @ W1^T) + lrelu((h*hn) @ W2^T)
// smem: WI[k][j] = (W1[j][k], W2[j][k]) float2, row stride 129 float2
//       AM[r][k] = (h+hn, h*hn)          float2, row stride 128 float2
// thread (tx=tid&15, ty=tid>>4): rows r0=ty*4 .. +3, cols j = tx + 16*jj (jj=0..7)
// inner: acc[i][jj] (packed f32x2) += (a,m) * (w1,w2)   -> one FFMA2 does both GEMMs

__device__ __forceinline__ float lrelu(float x) { return x > 0.f ? x : 0.01f * x; }

__device__ __forceinline__ void ffma2(unsigned long long& d,
                                      unsigned long long a,
                                      unsigned long long b) {
    asm("fma.rn.f32x2 %0, %1, %2, %0;" : "+l"(d) : "l"(a), "l"(b));
}

#define TILE_ROWS 64
#define W_STRIDE 129            // float2 units; 1032B rows -> 2-way transpose writes

__global__ void fused_gemm_kernel(const float* __restrict__ nfeat,
                                  const float* __restrict__ W1,
                                  const float* __restrict__ W2,
                                  const float* __restrict__ hn,
                                  float* __restrict__ out) {
    extern __shared__ float2 smem2[];
    float2* WI = smem2;                       // [128][W_STRIDE]
    float2* AM = smem2 + 128 * W_STRIDE;      // [64][128]

    int tid = threadIdx.x;
    int tx  = tid & 15;
    int ty  = tid >> 4;
    int r0  = ty * 4;

    // load + transpose + interleave weights (once per block)
    for (int idx = tid; idx < 128 * 128; idx += 256) {
        int c = idx >> 7;        // output column
        int k = idx & 127;       // input feature
        WI[k * W_STRIDE + c] = make_float2(W1[idx], W2[idx]);
    }

    const int n_tiles = (N_NODES + TILE_ROWS - 1) / TILE_ROWS;
    for (int tile = blockIdx.x; tile < n_tiles; tile += gridDim.x) {
        int n0 = tile * TILE_ROWS;
        __syncthreads();   // also covers first-iteration weight staging

        // stage AM = (h+hn, h*hn) interleaved
        for (int idx = tid; idx < TILE_ROWS * 32; idx += 256) {
            int r  = idx >> 5;
            int c4 = idx & 31;       // float4 chunk within row
            int g  = n0 + r;
            float4 hv = make_float4(0.f, 0.f, 0.f, 0.f);
            float4 nv = hv;
            if (g < N_NODES) {
                hv = __ldg(((const float4*)(nfeat + (size_t)g * D)) + c4);
                nv = __ldg(((const float4*)(hn   + (size_t)g * D)) + c4);
            }
            float4 p0, p1;
            p0.x = hv.x + nv.x; p0.y = hv.x * nv.x;
            p0.z = hv.y + nv.y; p0.w = hv.y * nv.y;
            p1.x = hv.z + nv.z; p1.y = hv.z * nv.z;
            p1.z = hv.w + nv.w; p1.w = hv.w * nv.w;
            float4* dst4 = (float4*)(AM + r * 128 + c4 * 4);
            dst4[0] = p0;
            dst4[1] = p1;
        }
        __syncthreads();

        unsigned long long acc[4][8];
        #pragma unroll
        for (int i = 0; i < 4; i++)
            #pragma unroll
            for (int j = 0; j < 8; j++) acc[i][j] = 0ULL;

        const unsigned long long* AMu = (const unsigned long long*)(AM + r0 * 128);
        const unsigned long long* WIu = (const unsigned long long*)WI;

        #pragma unroll 4
        for (int k = 0; k < 128; k++) {
            unsigned long long am[4];
            #pragma unroll
            for (int i = 0; i < 4; i++) am[i] = AMu[i * 128 + k];
            unsigned long long wv[8];
            const unsigned long long* wrow = WIu + k * W_STRIDE + tx;
            #pragma unroll
            for (int jj = 0; jj < 8; jj++) wv[jj] = wrow[jj * 16];
            #pragma unroll
            for (int i = 0; i < 4; i++)
                #pragma unroll
                for (int jj = 0; jj < 8; jj++)
                    ffma2(acc[i][jj], am[i], wv[jj]);
        }

        #pragma unroll
        for (int i = 0; i < 4; i++) {
            int g = n0 + r0 + i;
            if (g < N_NODES) {
                float* op = out + (size_t)g * D + tx;
                #pragma unroll
                for (int jj = 0; jj < 8; jj++) {
                    float2 pr = *(float2*)&acc[i][jj];
                    op[jj * 16] = lrelu(pr.x) + lrelu(pr.y);
                }
            }
        }
    }
}

// ---------------- launch ----------------
extern "C" void kernel_launch(void* const* d_in, const int* in_sizes, int n_in,
                              void* d_out, int out_size) {
    const float* nfeat = (const float*)d_in[0];
    const float* w     = (const float*)d_in[1];
    const float* W1    = (const float*)d_in[2];
    const float* W2    = (const float*)d_in[3];
    const void*  src   = d_in[4];
    const void*  dst   = d_in[5];

    float* outbuf = (float*)d_out;
    float* hn     = outbuf;                           // first N*D floats: h_neighbor
    float* out2   = outbuf + (size_t)N_NODES * D;     // second N*D floats: out

    zero_detect_kernel<<<(N_NODES + 255) / 256, 256>>>(src, dst);
    count_kernel<<<(N_EDGES + 255) / 256, 256>>>(dst);
    scan_lookback_kernel<<<SCAN_NBLK, 256>>>();
    scatter_kernel<<<(N_EDGES + 255) / 256, 256>>>(src, dst, w);
    aggregate_kernel<<<(N_NODES * 32 + 255) / 256, 256>>>(nfeat, hn);

    size_t smem_bytes = (size_t)(128 * W_STRIDE + TILE_ROWS * 128) * sizeof(float2);
    cudaFuncSetAttribute(fused_gemm_kernel,
                         cudaFuncAttributeMaxDynamicSharedMemorySize, (int)smem_bytes);
    fused_gemm_kernel<<<148, 256, smem_bytes>>>(nfeat, W1, W2, hn, out2);
}

// round 4
// speedup vs baseline: 1.8468x; 1.0087x over previous
#include <cuda_runtime.h>
#include <cstdint>

#define N_NODES 50000
#define N_EDGES 640000
#define D 128

#define SCAN_TILE 1024
#define SCAN_NBLK ((N_NODES + SCAN_TILE - 1) / SCAN_TILE)   // 49

typedef unsigned long long ULL;

// ---------------- device scratch (no allocations allowed) ----------------
__device__ int                g_is64;
__device__ int                g_count[N_NODES];
__device__ int                g_offsets[N_NODES + 1];
__device__ int                g_cursor[N_NODES];
__device__ unsigned int       g_scanstate[SCAN_NBLK];   // bit31 = ready, low bits = block sum
__device__ ULL                g_edge_sorted[N_EDGES];   // (w_bits<<32) | src

// Read an edge index that may be stored as int32 or int64.
__device__ __forceinline__ int edge_idx(const void* p, int i, int is64) {
    if (is64) return (int)__ldg(((const long long*)p) + i);
    return __ldg(((const int*)p) + i);
}

// ---------------- init: zero counts + scan state, detect index dtype ----------------
__global__ void zero_detect_kernel(const void* src, const void* dst) {
    int i = blockIdx.x * blockDim.x + threadIdx.x;
    if (i < N_NODES) g_count[i] = 0;
    if (i < SCAN_NBLK) g_scanstate[i] = 0u;
    if (i == 0) {
        g_offsets[N_NODES] = N_EDGES;
        const long long* s = (const long long*)src;
        const long long* d = (const long long*)dst;
        bool ok = true;
        for (int j = 0; j < 8; j++) {
            long long a = s[j], b = d[j];
            if (a < 0 || a >= N_NODES || b < 0 || b >= N_NODES) { ok = false; break; }
        }
        g_is64 = ok ? 1 : 0;
    }
}

__global__ void count_kernel(const void* dst) {
    int e = blockIdx.x * blockDim.x + threadIdx.x;
    if (e >= N_EDGES) return;
    int is64 = g_is64;
    atomicAdd(&g_count[edge_idx(dst, e, is64)], 1);
}

// ---------------- single-pass exclusive scan with decoupled lookback ----------------
__global__ void scan_lookback_kernel() {
    __shared__ int warpsums[8];
    __shared__ int blockexcl;
    int t    = threadIdx.x;
    int lane = t & 31;
    int wrp  = t >> 5;
    int b    = blockIdx.x;
    int base = b * SCAN_TILE + t * 4;

    int c[4];
    int lsum = 0;
    #pragma unroll
    for (int i = 0; i < 4; i++) {
        int idx = base + i;
        c[i] = (idx < N_NODES) ? g_count[idx] : 0;
        lsum += c[i];
    }
    int incl = lsum;
    #pragma unroll
    for (int o = 1; o < 32; o <<= 1) {
        int v = __shfl_up_sync(0xFFFFFFFF, incl, o);
        if (lane >= o) incl += v;
    }
    if (lane == 31) warpsums[wrp] = incl;
    __syncthreads();

    if (t == 0) {
        int tot = 0;
        #pragma unroll
        for (int wv = 0; wv < 8; wv++) tot += warpsums[wv];
        atomicExch(&g_scanstate[b], 0x80000000u | (unsigned)tot);
    }

    if (wrp == 0) {
        int psum = 0;
        for (int p = lane; p < b; p += 32) {
            unsigned v;
            do { v = atomicOr(&g_scanstate[p], 0u); } while (!(v & 0x80000000u));
            psum += (int)(v & 0x7FFFFFFFu);
        }
        #pragma unroll
        for (int o = 16; o > 0; o >>= 1) psum += __shfl_down_sync(0xFFFFFFFF, psum, o);
        if (lane == 0) blockexcl = psum;
    }
    __syncthreads();

    int wbase = 0;
    #pragma unroll
    for (int wv = 0; wv < 8; wv++) {
        int v = warpsums[wv];
        if (wv < wrp) wbase += v;
    }
    int run = blockexcl + wbase + (incl - lsum);
    #pragma unroll
    for (int i = 0; i < 4; i++) {
        int idx = base + i;
        if (idx < N_NODES) {
            g_offsets[idx] = run;
            g_cursor[idx]  = run;
            run += c[i];
        }
    }
}

__global__ void scatter_kernel(const void* src, const void* dst, const float* __restrict__ w) {
    int e = blockIdx.x * blockDim.x + threadIdx.x;
    if (e >= N_EDGES) return;
    int is64 = g_is64;
    int d = edge_idx(dst, e, is64);
    int s = edge_idx(src, e, is64);
    float wv = __ldg(w + e);
    int pos = atomicAdd(&g_cursor[d], 1);
    g_edge_sorted[pos] = ((ULL)__float_as_uint(wv) << 32) | (unsigned)s;
}

// ---------------- per-node aggregation: one warp per node, unroll 4 ----------------
__global__ void aggregate_kernel(const float* __restrict__ nfeat, float* __restrict__ hn) {
    int gwarp = (blockIdx.x * blockDim.x + threadIdx.x) >> 5;
    int lane  = threadIdx.x & 31;
    if (gwarp >= N_NODES) return;
    int beg = g_offsets[gwarp];
    int end = g_offsets[gwarp + 1];
    float4 acc = make_float4(0.f, 0.f, 0.f, 0.f);
    int e = beg;
    for (; e + 3 < end; e += 4) {
        ULL p0 = __ldg(&g_edge_sorted[e]);
        ULL p1 = __ldg(&g_edge_sorted[e + 1]);
        ULL p2 = __ldg(&g_edge_sorted[e + 2]);
        ULL p3 = __ldg(&g_edge_sorted[e + 3]);
        float4 v0 = __ldg(((const float4*)(nfeat + (size_t)(unsigned)(p0 & 0xFFFFFFFFu) * D)) + lane);
        float4 v1 = __ldg(((const float4*)(nfeat + (size_t)(unsigned)(p1 & 0xFFFFFFFFu) * D)) + lane);
        float4 v2 = __ldg(((const float4*)(nfeat + (size_t)(unsigned)(p2 & 0xFFFFFFFFu) * D)) + lane);
        float4 v3 = __ldg(((const float4*)(nfeat + (size_t)(unsigned)(p3 & 0xFFFFFFFFu) * D)) + lane);
        float w0 = __uint_as_float((unsigned)(p0 >> 32));
        float w1 = __uint_as_float((unsigned)(p1 >> 32));
        float w2 = __uint_as_float((unsigned)(p2 >> 32));
        float w3 = __uint_as_float((unsigned)(p3 >> 32));
        acc.x += w0 * v0.x; acc.y += w0 * v0.y; acc.z += w0 * v0.z; acc.w += w0 * v0.w;
        acc.x += w1 * v1.x; acc.y += w1 * v1.y; acc.z += w1 * v1.z; acc.w += w1 * v1.w;
        acc.x += w2 * v2.x; acc.y += w2 * v2.y; acc.z += w2 * v2.z; acc.w += w2 * v2.w;
        acc.x += w3 * v3.x; acc.y += w3 * v3.y; acc.z += w3 * v3.z; acc.w += w3 * v3.w;
    }
    for (; e < end; e++) {
        ULL p0 = __ldg(&g_edge_sorted[e]);
        float4 v0 = __ldg(((const float4*)(nfeat + (size_t)(unsigned)(p0 & 0xFFFFFFFFu) * D)) + lane);
        float w0 = __uint_as_float((unsigned)(p0 >> 32));
        acc.x += w0 * v0.x; acc.y += w0 * v0.y; acc.z += w0 * v0.z; acc.w += w0 * v0.w;
    }
    ((float4*)(hn + (size_t)gwarp * D))[lane] = acc;
}

// ---------------- fused bi-interaction GEMM, f32x2 packed, software-pipelined ----------------
__device__ __forceinline__ float lrelu(float x) { return x > 0.f ? x : 0.01f * x; }

__device__ __forceinline__ void ffma2(ULL& d, ULL a, ULL b) {
    asm("fma.rn.f32x2 %0, %1, %2, %0;" : "+l"(d) : "l"(a), "l"(b));
}

#define TILE_ROWS 64
#define W_STRIDE 129            // float2 units
#define NSTG 8                  // staging chunks per thread (64*32/256)

__global__ void __launch_bounds__(256, 1)
fused_gemm_kernel(const float* __restrict__ nfeat,
                  const float* __restrict__ W1,
                  const float* __restrict__ W2,
                  const float* __restrict__ hn,
                  float* __restrict__ out) {
    extern __shared__ float2 smem2[];
    float2* WI = smem2;                       // [128][W_STRIDE]
    float2* AM = smem2 + 128 * W_STRIDE;      // [64][128]

    int tid = threadIdx.x;
    int tx  = tid & 15;
    int ty  = tid >> 4;
    int r0  = ty * 4;

    // load + transpose + interleave weights (once per block)
    for (int idx = tid; idx < 128 * 128; idx += 256) {
        int c = idx >> 7;
        int k = idx & 127;
        WI[k * W_STRIDE + c] = make_float2(W1[idx], W2[idx]);
    }

    const int n_tiles = (N_NODES + TILE_ROWS - 1) / TILE_ROWS;

    float4 sp0[NSTG], sp1[NSTG];

    // prologue: prefetch first tile into registers
    int tile = blockIdx.x;
    if (tile < n_tiles) {
        int n0 = tile * TILE_ROWS;
        #pragma unroll
        for (int q = 0; q < NSTG; q++) {
            int idx = tid + q * 256;
            int r  = idx >> 5;
            int c4 = idx & 31;
            int g  = n0 + r;
            float4 hv = make_float4(0.f, 0.f, 0.f, 0.f);
            float4 nv = hv;
            if (g < N_NODES) {
                hv = __ldg(((const float4*)(nfeat + (size_t)g * D)) + c4);
                nv = __ldg(((const float4*)(hn   + (size_t)g * D)) + c4);
            }
            sp0[q] = make_float4(hv.x + nv.x, hv.x * nv.x, hv.y + nv.y, hv.y * nv.y);
            sp1[q] = make_float4(hv.z + nv.z, hv.z * nv.z, hv.w + nv.w, hv.w * nv.w);
        }
    }
    __syncthreads();   // weights staged

    for (; tile < n_tiles; tile += gridDim.x) {
        // commit prefetched tile to smem
        #pragma unroll
        for (int q = 0; q < NSTG; q++) {
            int idx = tid + q * 256;
            float4* dst4 = (float4*)(AM + (idx >> 5) * 128 + (idx & 31) * 4);
            dst4[0] = sp0[q];
            dst4[1] = sp1[q];
        }
        __syncthreads();

        // prefetch NEXT tile into registers (LDGs fly during compute below)
        int next = tile + gridDim.x;
        if (next < n_tiles) {
            int n0 = next * TILE_ROWS;
            #pragma unroll
            for (int q = 0; q < NSTG; q++) {
                int idx = tid + q * 256;
                int r  = idx >> 5;
                int c4 = idx & 31;
                int g  = n0 + r;
                float4 hv = make_float4(0.f, 0.f, 0.f, 0.f);
                float4 nv = hv;
                if (g < N_NODES) {
                    hv = __ldg(((const float4*)(nfeat + (size_t)g * D)) + c4);
                    nv = __ldg(((const float4*)(hn   + (size_t)g * D)) + c4);
                }
                sp0[q] = make_float4(hv.x + nv.x, hv.x * nv.x, hv.y + nv.y, hv.y * nv.y);
                sp1[q] = make_float4(hv.z + nv.z, hv.z * nv.z, hv.w + nv.w, hv.w * nv.w);
            }
        }

        // compute
        ULL acc[4][8];
        #pragma unroll
        for (int i = 0; i < 4; i++)
            #pragma unroll
            for (int j = 0; j < 8; j++) acc[i][j] = 0ULL;

        const ULL* AMu = (const ULL*)(AM + r0 * 128);
        const ULL* WIu = (const ULL*)WI;

        #pragma unroll 2
        for (int k = 0; k < 128; k += 2) {
            ULL am0[4], am1[4];
            #pragma unroll
            for (int i = 0; i < 4; i++) {
                ulonglong2 v = *(const ulonglong2*)(AMu + i * 128 + k);
                am0[i] = v.x;
                am1[i] = v.y;
            }
            const ULL* wrow0 = WIu + k * W_STRIDE + tx;
            const ULL* wrow1 = wrow0 + W_STRIDE;
            ULL wv0[8], wv1[8];
            #pragma unroll
            for (int jj = 0; jj < 8; jj++) {
                wv0[jj] = wrow0[jj * 16];
                wv1[jj] = wrow1[jj * 16];
            }
            #pragma unroll
            for (int i = 0; i < 4; i++)
                #pragma unroll
                for (int jj = 0; jj < 8; jj++) {
                    ffma2(acc[i][jj], am0[i], wv0[jj]);
                    ffma2(acc[i][jj], am1[i], wv1[jj]);
                }
        }

        // epilogue
        int n0 = tile * TILE_ROWS;
        #pragma unroll
        for (int i = 0; i < 4; i++) {
            int g = n0 + r0 + i;
            if (g < N_NODES) {
                float* op = out + (size_t)g * D + tx;
                #pragma unroll
                for (int jj = 0; jj < 8; jj++) {
                    float2 pr = *(float2*)&acc[i][jj];
                    op[jj * 16] = lrelu(pr.x) + lrelu(pr.y);
                }
            }
        }
        __syncthreads();   // protect AM before next commit
    }
}

// ---------------- launch ----------------
extern "C" void kernel_launch(void* const* d_in, const int* in_sizes, int n_in,
                              void* d_out, int out_size) {
    const float* nfeat = (const float*)d_in[0];
    const float* w     = (const float*)d_in[1];
    const float* W1    = (const float*)d_in[2];
    const float* W2    = (const float*)d_in[3];
    const void*  src   = d_in[4];
    const void*  dst   = d_in[5];

    float* outbuf = (float*)d_out;
    float* hn     = outbuf;                           // first N*D floats: h_neighbor
    float* out2   = outbuf + (size_t)N_NODES * D;     // second N*D floats: out

    zero_detect_kernel<<<(N_NODES + 255) / 256, 256>>>(src, dst);
    count_kernel<<<(N_EDGES + 255) / 256, 256>>>(dst);
    scan_lookback_kernel<<<SCAN_NBLK, 256>>>();
    scatter_kernel<<<(N_EDGES + 255) / 256, 256>>>(src, dst, w);
    aggregate_kernel<<<(N_NODES * 32 + 255) / 256, 256>>>(nfeat, hn);

    size_t smem_bytes = (size_t)(128 * W_STRIDE + TILE_ROWS * 128) * sizeof(float2);
    cudaFuncSetAttribute(fused_gemm_kernel,
                         cudaFuncAttributeMaxDynamicSharedMemorySize, (int)smem_bytes);
    fused_gemm_kernel<<<148, 256, smem_bytes>>>(nfeat, W1, W2, hn, out2);
}

// round 7
// speedup vs baseline: 1.8991x; 1.0283x over previous
#include <cuda_runtime.h>
#include <cuda_bf16.h>
#include <cstdint>

#define N_NODES 50000
#define N_EDGES 640000
#define D 128

#define SCAN_TILE 1024
#define SCAN_NBLK ((N_NODES + SCAN_TILE - 1) / SCAN_TILE)   // 49

typedef unsigned long long ULL;

// ---------------- device scratch (no allocations allowed) ----------------
__device__ int                g_is64;
__device__ int                g_count[N_NODES];
__device__ int                g_offsets[N_NODES + 1];
__device__ int                g_cursor[N_NODES];
__device__ unsigned int       g_scanstate[SCAN_NBLK];
__device__ ULL                g_edge_sorted[N_EDGES];   // (w_bits<<32) | src

__device__ __forceinline__ int edge_idx(const void* p, int i, int is64) {
    if (is64) return (int)__ldg(((const long long*)p) + i);
    return __ldg(((const int*)p) + i);
}

// ---------------- init ----------------
__global__ void zero_detect_kernel(const void* src, const void* dst) {
    int i = blockIdx.x * blockDim.x + threadIdx.x;
    if (i < N_NODES) g_count[i] = 0;
    if (i < SCAN_NBLK) g_scanstate[i] = 0u;
    if (i == 0) {
        g_offsets[N_NODES] = N_EDGES;
        const long long* s = (const long long*)src;
        const long long* d = (const long long*)dst;
        bool ok = true;
        for (int j = 0; j < 8; j++) {
            long long a = s[j], b = d[j];
            if (a < 0 || a >= N_NODES || b < 0 || b >= N_NODES) { ok = false; break; }
        }
        g_is64 = ok ? 1 : 0;
    }
}

__global__ void count_kernel(const void* dst) {
    int e = blockIdx.x * blockDim.x + threadIdx.x;
    if (e >= N_EDGES) return;
    int is64 = g_is64;
    atomicAdd(&g_count[edge_idx(dst, e, is64)], 1);
}

// ---------------- single-pass exclusive scan, decoupled lookback ----------------
__global__ void scan_lookback_kernel() {
    __shared__ int warpsums[8];
    __shared__ int blockexcl;
    int t    = threadIdx.x;
    int lane = t & 31;
    int wrp  = t >> 5;
    int b    = blockIdx.x;
    int base = b * SCAN_TILE + t * 4;

    int c[4];
    int lsum = 0;
    #pragma unroll
    for (int i = 0; i < 4; i++) {
        int idx = base + i;
        c[i] = (idx < N_NODES) ? g_count[idx] : 0;
        lsum += c[i];
    }
    int incl = lsum;
    #pragma unroll
    for (int o = 1; o < 32; o <<= 1) {
        int v = __shfl_up_sync(0xFFFFFFFF, incl, o);
        if (lane >= o) incl += v;
    }
    if (lane == 31) warpsums[wrp] = incl;
    __syncthreads();

    if (t == 0) {
        int tot = 0;
        #pragma unroll
        for (int wv = 0; wv < 8; wv++) tot += warpsums[wv];
        atomicExch(&g_scanstate[b], 0x80000000u | (unsigned)tot);
    }
    if (wrp == 0) {
        int psum = 0;
        for (int p = lane; p < b; p += 32) {
            unsigned v;
            do { v = atomicOr(&g_scanstate[p], 0u); } while (!(v & 0x80000000u));
            psum += (int)(v & 0x7FFFFFFFu);
        }
        #pragma unroll
        for (int o = 16; o > 0; o >>= 1) psum += __shfl_down_sync(0xFFFFFFFF, psum, o);
        if (lane == 0) blockexcl = psum;
    }
    __syncthreads();

    int wbase = 0;
    #pragma unroll
    for (int wv = 0; wv < 8; wv++) {
        int v = warpsums[wv];
        if (wv < wrp) wbase += v;
    }
    int run = blockexcl + wbase + (incl - lsum);
    #pragma unroll
    for (int i = 0; i < 4; i++) {
        int idx = base + i;
        if (idx < N_NODES) {
            g_offsets[idx] = run;
            g_cursor[idx]  = run;
            run += c[i];
        }
    }
}

__global__ void scatter_kernel(const void* src, const void* dst, const float* __restrict__ w) {
    int e = blockIdx.x * blockDim.x + threadIdx.x;
    if (e >= N_EDGES) return;
    int is64 = g_is64;
    int d = edge_idx(dst, e, is64);
    int s = edge_idx(src, e, is64);
    float wv = __ldg(w + e);
    int pos = atomicAdd(&g_cursor[d], 1);
    g_edge_sorted[pos] = ((ULL)__float_as_uint(wv) << 32) | (unsigned)s;
}

// ---------------- per-node aggregation: one warp per node ----------------
__global__ void aggregate_kernel(const float* __restrict__ nfeat, float* __restrict__ hn) {
    int gwarp = (blockIdx.x * blockDim.x + threadIdx.x) >> 5;
    int lane  = threadIdx.x & 31;
    if (gwarp >= N_NODES) return;
    int beg = g_offsets[gwarp];
    int end = g_offsets[gwarp + 1];
    float4 acc = make_float4(0.f, 0.f, 0.f, 0.f);
    int e = beg;
    for (; e + 3 < end; e += 4) {
        ULL p0 = __ldg(&g_edge_sorted[e]);
        ULL p1 = __ldg(&g_edge_sorted[e + 1]);
        ULL p2 = __ldg(&g_edge_sorted[e + 2]);
        ULL p3 = __ldg(&g_edge_sorted[e + 3]);
        float4 v0 = __ldg(((const float4*)(nfeat + (size_t)(unsigned)(p0 & 0xFFFFFFFFu) * D)) + lane);
        float4 v1 = __ldg(((const float4*)(nfeat + (size_t)(unsigned)(p1 & 0xFFFFFFFFu) * D)) + lane);
        float4 v2 = __ldg(((const float4*)(nfeat + (size_t)(unsigned)(p2 & 0xFFFFFFFFu) * D)) + lane);
        float4 v3 = __ldg(((const float4*)(nfeat + (size_t)(unsigned)(p3 & 0xFFFFFFFFu) * D)) + lane);
        float w0 = __uint_as_float((unsigned)(p0 >> 32));
        float w1 = __uint_as_float((unsigned)(p1 >> 32));
        float w2 = __uint_as_float((unsigned)(p2 >> 32));
        float w3 = __uint_as_float((unsigned)(p3 >> 32));
        acc.x += w0 * v0.x; acc.y += w0 * v0.y; acc.z += w0 * v0.z; acc.w += w0 * v0.w;
        acc.x += w1 * v1.x; acc.y += w1 * v1.y; acc.z += w1 * v1.z; acc.w += w1 * v1.w;
        acc.x += w2 * v2.x; acc.y += w2 * v2.y; acc.z += w2 * v2.z; acc.w += w2 * v2.w;
        acc.x += w3 * v3.x; acc.y += w3 * v3.y; acc.z += w3 * v3.z; acc.w += w3 * v3.w;
    }
    for (; e < end; e++) {
        ULL p0 = __ldg(&g_edge_sorted[e]);
        float4 v0 = __ldg(((const float4*)(nfeat + (size_t)(unsigned)(p0 & 0xFFFFFFFFu) * D)) + lane);
        float w0 = __uint_as_float((unsigned)(p0 >> 32));
        acc.x += w0 * v0.x; acc.y += w0 * v0.y; acc.z += w0 * v0.z; acc.w += w0 * v0.w;
    }
    ((float4*)(hn + (size_t)gwarp * D))[lane] = acc;
}

// ================= mma.sync bi-interaction GEMM (HMMA, sm_100-base safe) =========
// out = lrelu((h+hn) @ W1^T) + lrelu((h*hn) @ W2^T)
// bf16 3-product split per branch: AhiBhi + AhiBlo + AloBhi, fp32 accumulate.

#define PAD 136                          // bf16 elems per row (272B) -> conflict-free frags
#define TILE_BYTES (128 * PAD * 2)       // 34816 per tile
#define SA_HI  0
#define SA_LO  (TILE_BYTES)
#define SW1_HI (2 * TILE_BYTES)
#define SW1_LO (3 * TILE_BYTES)
#define SW2_HI (4 * TILE_BYTES)
#define SW2_LO (5 * TILE_BYTES)
#define SM_TOTAL (6 * TILE_BYTES)        // 208896 B

__device__ __forceinline__ float lrelu(float x) { return x > 0.f ? x : 0.01f * x; }
__device__ __forceinline__ unsigned pack2(float a, float b) {
    unsigned short ua = __bfloat16_as_ushort(__float2bfloat16_rn(a));
    unsigned short ub = __bfloat16_as_ushort(__float2bfloat16_rn(b));
    return (unsigned)ua | ((unsigned)ub << 16);
}
__device__ __forceinline__ float bflo(float x) {
    return x - __bfloat162float(__float2bfloat16_rn(x));
}

__device__ __forceinline__ void mma16816(float* c, const unsigned* a, const unsigned* b) {
    asm volatile(
        "mma.sync.aligned.m16n8k16.row.col.f32.bf16.bf16.f32 "
        "{%0,%1,%2,%3}, {%4,%5,%6,%7}, {%8,%9}, {%0,%1,%2,%3};"
        : "+f"(c[0]), "+f"(c[1]), "+f"(c[2]), "+f"(c[3])
        : "r"(a[0]), "r"(a[1]), "r"(a[2]), "r"(a[3]), "r"(b[0]), "r"(b[1]));
}

// store one fp32 value's hi/lo bf16 pair-pack into padded smem tile at (r, k even)
__device__ __forceinline__ void st_pairs(char* smem, int base, int r, int k,
                                         float x0, float x1, float x2, float x3,
                                         int lo_base) {
    unsigned* hp = (unsigned*)(smem + base + r * (PAD * 2) + k * 2);
    hp[0] = pack2(x0, x1);
    hp[1] = pack2(x2, x3);
    unsigned* lp = (unsigned*)(smem + lo_base + r * (PAD * 2) + k * 2);
    lp[0] = pack2(bflo(x0), bflo(x1));
    lp[1] = pack2(bflo(x2), bflo(x3));
}

__global__ void __launch_bounds__(256, 1)
mma_gemm_kernel(const float* __restrict__ nfeat,
                const float* __restrict__ W1,
                const float* __restrict__ W2,
                const float* __restrict__ hn,
                float* __restrict__ out) {
    extern __shared__ char smem[];
    int tid  = threadIdx.x;
    int wid  = tid >> 5;
    int lane = tid & 31;
    int g8   = lane >> 2;        // 0..7
    int t4   = lane & 3;         // 0..3

    int warp_r = wid >> 2;       // 0..1  -> row base warp_r*64
    int warp_c = wid & 3;        // 0..3  -> col base warp_c*32

    // ---- stage weight splits once ----
    {
        int r  = tid >> 1;           // 0..127 (output col)
        int kc = (tid & 1) * 64;
        const float4* w1p = (const float4*)(W1 + (size_t)r * D + kc);
        const float4* w2p = (const float4*)(W2 + (size_t)r * D + kc);
        #pragma unroll
        for (int i = 0; i < 16; i++) {
            float4 a = __ldg(w1p + i);
            float4 b = __ldg(w2p + i);
            int k = kc + i * 4;
            st_pairs(smem, SW1_HI, r, k, a.x, a.y, a.z, a.w, SW1_LO);
            st_pairs(smem, SW2_HI, r, k, b.x, b.y, b.z, b.w, SW2_LO);
        }
    }
    __syncthreads();

    const int n_tiles = (N_NODES + 127) / 128;   // 391

    for (int tile = blockIdx.x; tile < n_tiles; tile += gridDim.x) {
        int n0 = tile * 128;

        float acc[2][4][4][4];   // [branch][mi][ni][frag]
        #pragma unroll
        for (int b = 0; b < 2; b++)
            #pragma unroll
            for (int mi = 0; mi < 4; mi++)
                #pragma unroll
                for (int ni = 0; ni < 4; ni++)
                    #pragma unroll
                    for (int f = 0; f < 4; f++) acc[b][mi][ni][f] = 0.f;

        #pragma unroll
        for (int branch = 0; branch < 2; branch++) {
            // ---- stage A (h+hn or h*hn) hi/lo ----
            {
                int r  = tid >> 1;
                int kc = (tid & 1) * 64;
                int g  = n0 + r;
                const float4* hp = (const float4*)(nfeat + (size_t)g * D + kc);
                const float4* np = (const float4*)(hn    + (size_t)g * D + kc);
                #pragma unroll
                for (int i = 0; i < 16; i++) {
                    float4 v = make_float4(0.f, 0.f, 0.f, 0.f);
                    if (g < N_NODES) {
                        float4 hv = __ldg(hp + i);
                        float4 nv = __ldg(np + i);
                        v = (branch == 0)
                          ? make_float4(hv.x + nv.x, hv.y + nv.y, hv.z + nv.z, hv.w + nv.w)
                          : make_float4(hv.x * nv.x, hv.y * nv.y, hv.z * nv.z, hv.w * nv.w);
                    }
                    st_pairs(smem, SA_HI, r, kc + i * 4, v.x, v.y, v.z, v.w, SA_LO);
                }
            }
            __syncthreads();

            // ---- 3 product passes: (Ahi,Bhi), (Ahi,Blo), (Alo,Bhi) ----
            #pragma unroll
            for (int p = 0; p < 3; p++) {
                const char* As = smem + ((p == 2) ? SA_LO : SA_HI);
                const char* Bs = smem + ((branch == 0)
                                  ? ((p == 1) ? SW1_LO : SW1_HI)
                                  : ((p == 1) ? SW2_LO : SW2_HI));
                #pragma unroll
                for (int kk = 0; kk < 8; kk++) {
                    int kb = kk * 16;
                    unsigned afr[4][4];
                    #pragma unroll
                    for (int mi = 0; mi < 4; mi++) {
                        int r0 = warp_r * 64 + mi * 16 + g8;
                        const char* base = As + (size_t)r0 * (PAD * 2) + (kb + t4 * 2) * 2;
                        afr[mi][0] = *(const unsigned*)base;
                        afr[mi][1] = *(const unsigned*)(base + 8 * (PAD * 2));
                        afr[mi][2] = *(const unsigned*)(base + 16);
                        afr[mi][3] = *(const unsigned*)(base + 8 * (PAD * 2) + 16);
                    }
                    unsigned bfr[4][2];
                    #pragma unroll
                    for (int ni = 0; ni < 4; ni++) {
                        int c0 = warp_c * 32 + ni * 8 + g8;
                        const char* base = Bs + (size_t)c0 * (PAD * 2) + (kb + t4 * 2) * 2;
                        bfr[ni][0] = *(const unsigned*)base;
                        bfr[ni][1] = *(const unsigned*)(base + 16);
                    }
                    #pragma unroll
                    for (int mi = 0; mi < 4; mi++)
                        #pragma unroll
                        for (int ni = 0; ni < 4; ni++)
                            mma16816(acc[branch][mi][ni], afr[mi], bfr[ni]);
                }
            }
            __syncthreads();   // done reading A before next branch restages
        }

        // ---- epilogue: lrelu(add) + lrelu(mul), write fp32 ----
        #pragma unroll
        for (int mi = 0; mi < 4; mi++) {
            int r_lo = n0 + warp_r * 64 + mi * 16 + g8;
            int r_hi = r_lo + 8;
            #pragma unroll
            for (int ni = 0; ni < 4; ni++) {
                int c0 = warp_c * 32 + ni * 8 + t4 * 2;
                if (r_lo < N_NODES) {
                    float2 o;
                    o.x = lrelu(acc[0][mi][ni][0]) + lrelu(acc[1][mi][ni][0]);
                    o.y = lrelu(acc[0][mi][ni][1]) + lrelu(acc[1][mi][ni][1]);
                    *(float2*)(out + (size_t)r_lo * D + c0) = o;
                }
                if (r_hi < N_NODES) {
                    float2 o;
                    o.x = lrelu(acc[0][mi][ni][2]) + lrelu(acc[1][mi][ni][2]);
                    o.y = lrelu(acc[0][mi][ni][3]) + lrelu(acc[1][mi][ni][3]);
                    *(float2*)(out + (size_t)r_hi * D + c0) = o;
                }
            }
        }
    }
}

// ---------------- launch ----------------
extern "C" void kernel_launch(void* const* d_in, const int* in_sizes, int n_in,
                              void* d_out, int out_size) {
    const float* nfeat = (const float*)d_in[0];
    const float* w     = (const float*)d_in[1];
    const float* W1    = (const float*)d_in[2];
    const float* W2    = (const float*)d_in[3];
    const void*  src   = d_in[4];
    const void*  dst   = d_in[5];

    float* outbuf = (float*)d_out;
    float* hn     = outbuf;                           // h_neighbor
    float* out2   = outbuf + (size_t)N_NODES * D;     // out

    zero_detect_kernel<<<(N_NODES + 255) / 256, 256>>>(src, dst);
    count_kernel<<<(N_EDGES + 255) / 256, 256>>>(dst);
    scan_lookback_kernel<<<SCAN_NBLK, 256>>>();
    scatter_kernel<<<(N_EDGES + 255) / 256, 256>>>(src, dst, w);
    aggregate_kernel<<<(N_NODES * 32 + 255) / 256, 256>>>(nfeat, hn);

    cudaFuncSetAttribute(mma_gemm_kernel,
                         cudaFuncAttributeMaxDynamicSharedMemorySize, SM_TOTAL);
    mma_gemm_kernel<<<148, 256, SM_TOTAL>>>(nfeat, W1, W2, hn, out2);
}

// round 9
// speedup vs baseline: 2.0147x; 1.0608x over previous
#include <cuda_runtime.h>
#include <cuda_bf16.h>
#include <cstdint>

#define N_NODES 50000
#define N_EDGES 640000
#define D 128

#define SCAN_TILE 1024
#define SCAN_NBLK ((N_NODES + SCAN_TILE - 1) / SCAN_TILE)   // 49

typedef unsigned long long ULL;

// ---------------- device scratch (no allocations allowed) ----------------
__device__ int                g_is64;
__device__ int                g_count[N_NODES];
__device__ int                g_offsets[N_NODES + 1];
__device__ int                g_cursor[N_NODES];
__device__ unsigned int       g_scanstate[SCAN_NBLK];
__device__ ULL                g_edge_sorted[N_EDGES];   // (w_bits<<32) | src

__device__ __forceinline__ int edge_idx(const void* p, int i, int is64) {
    if (is64) return (int)__ldg(((const long long*)p) + i);
    return __ldg(((const int*)p) + i);
}

// ---------------- init ----------------
__global__ void zero_detect_kernel(const void* src, const void* dst) {
    int i = blockIdx.x * blockDim.x + threadIdx.x;
    if (i < N_NODES) g_count[i] = 0;
    if (i < SCAN_NBLK) g_scanstate[i] = 0u;
    if (i == 0) {
        g_offsets[N_NODES] = N_EDGES;
        const long long* s = (const long long*)src;
        const long long* d = (const long long*)dst;
        bool ok = true;
        for (int j = 0; j < 8; j++) {
            long long a = s[j], b = d[j];
            if (a < 0 || a >= N_NODES || b < 0 || b >= N_NODES) { ok = false; break; }
        }
        g_is64 = ok ? 1 : 0;
    }
}

__global__ void count_kernel(const void* dst) {
    int e = blockIdx.x * blockDim.x + threadIdx.x;
    if (e >= N_EDGES) return;
    int is64 = g_is64;
    atomicAdd(&g_count[edge_idx(dst, e, is64)], 1);
}

// ---------------- single-pass exclusive scan, decoupled lookback ----------------
__global__ void scan_lookback_kernel() {
    __shared__ int warpsums[8];
    __shared__ int blockexcl;
    int t    = threadIdx.x;
    int lane = t & 31;
    int wrp  = t >> 5;
    int b    = blockIdx.x;
    int base = b * SCAN_TILE + t * 4;

    int c[4];
    int lsum = 0;
    #pragma unroll
    for (int i = 0; i < 4; i++) {
        int idx = base + i;
        c[i] = (idx < N_NODES) ? g_count[idx] : 0;
        lsum += c[i];
    }
    int incl = lsum;
    #pragma unroll
    for (int o = 1; o < 32; o <<= 1) {
        int v = __shfl_up_sync(0xFFFFFFFF, incl, o);
        if (lane >= o) incl += v;
    }
    if (lane == 31) warpsums[wrp] = incl;
    __syncthreads();

    if (t == 0) {
        int tot = 0;
        #pragma unroll
        for (int wv = 0; wv < 8; wv++) tot += warpsums[wv];
        atomicExch(&g_scanstate[b], 0x80000000u | (unsigned)tot);
    }
    if (wrp == 0) {
        int psum = 0;
        for (int p = lane; p < b; p += 32) {
            unsigned v;
            do { v = atomicOr(&g_scanstate[p], 0u); } while (!(v & 0x80000000u));
            psum += (int)(v & 0x7FFFFFFFu);
        }
        #pragma unroll
        for (int o = 16; o > 0; o >>= 1) psum += __shfl_down_sync(0xFFFFFFFF, psum, o);
        if (lane == 0) blockexcl = psum;
    }
    __syncthreads();

    int wbase = 0;
    #pragma unroll
    for (int wv = 0; wv < 8; wv++) {
        int v = warpsums[wv];
        if (wv < wrp) wbase += v;
    }
    int run = blockexcl + wbase + (incl - lsum);
    #pragma unroll
    for (int i = 0; i < 4; i++) {
        int idx = base + i;
        if (idx < N_NODES) {
            g_offsets[idx] = run;
            g_cursor[idx]  = run;
            run += c[i];
        }
    }
}

__global__ void scatter_kernel(const void* src, const void* dst, const float* __restrict__ w) {
    int e = blockIdx.x * blockDim.x + threadIdx.x;
    if (e >= N_EDGES) return;
    int is64 = g_is64;
    int d = edge_idx(dst, e, is64);
    int s = edge_idx(src, e, is64);
    float wv = __ldg(w + e);
    int pos = atomicAdd(&g_cursor[d], 1);
    g_edge_sorted[pos] = ((ULL)__float_as_uint(wv) << 32) | (unsigned)s;
}

// ---------------- per-node aggregation: one warp per node ----------------
__global__ void aggregate_kernel(const float* __restrict__ nfeat, float* __restrict__ hn) {
    int gwarp = (blockIdx.x * blockDim.x + threadIdx.x) >> 5;
    int lane  = threadIdx.x & 31;
    if (gwarp >= N_NODES) return;
    int beg = g_offsets[gwarp];
    int end = g_offsets[gwarp + 1];
    float4 acc = make_float4(0.f, 0.f, 0.f, 0.f);
    int e = beg;
    for (; e + 3 < end; e += 4) {
        ULL p0 = __ldg(&g_edge_sorted[e]);
        ULL p1 = __ldg(&g_edge_sorted[e + 1]);
        ULL p2 = __ldg(&g_edge_sorted[e + 2]);
        ULL p3 = __ldg(&g_edge_sorted[e + 3]);
        float4 v0 = __ldg(((const float4*)(nfeat + (size_t)(unsigned)(p0 & 0xFFFFFFFFu) * D)) + lane);
        float4 v1 = __ldg(((const float4*)(nfeat + (size_t)(unsigned)(p1 & 0xFFFFFFFFu) * D)) + lane);
        float4 v2 = __ldg(((const float4*)(nfeat + (size_t)(unsigned)(p2 & 0xFFFFFFFFu) * D)) + lane);
        float4 v3 = __ldg(((const float4*)(nfeat + (size_t)(unsigned)(p3 & 0xFFFFFFFFu) * D)) + lane);
        float w0 = __uint_as_float((unsigned)(p0 >> 32));
        float w1 = __uint_as_float((unsigned)(p1 >> 32));
        float w2 = __uint_as_float((unsigned)(p2 >> 32));
        float w3 = __uint_as_float((unsigned)(p3 >> 32));
        acc.x += w0 * v0.x; acc.y += w0 * v0.y; acc.z += w0 * v0.z; acc.w += w0 * v0.w;
        acc.x += w1 * v1.x; acc.y += w1 * v1.y; acc.z += w1 * v1.z; acc.w += w1 * v1.w;
        acc.x += w2 * v2.x; acc.y += w2 * v2.y; acc.z += w2 * v2.z; acc.w += w2 * v2.w;
        acc.x += w3 * v3.x; acc.y += w3 * v3.y; acc.z += w3 * v3.z; acc.w += w3 * v3.w;
    }
    for (; e < end; e++) {
        ULL p0 = __ldg(&g_edge_sorted[e]);
        float4 v0 = __ldg(((const float4*)(nfeat + (size_t)(unsigned)(p0 & 0xFFFFFFFFu) * D)) + lane);
        float w0 = __uint_as_float((unsigned)(p0 >> 32));
        acc.x += w0 * v0.x; acc.y += w0 * v0.y; acc.z += w0 * v0.z; acc.w += w0 * v0.w;
    }
    ((float4*)(hn + (size_t)gwarp * D))[lane] = acc;
}

// ================= mma.sync bi-interaction GEMM with ldmatrix =================
// out = lrelu((h+hn) @ W1^T) + lrelu((h*hn) @ W2^T)
// bf16 3-product split per branch: AhiBhi + AhiBlo + AloBhi, fp32 accumulate.
// Fragments loaded via ldmatrix.x4 (1 issue per 4 8x8 matrices).

#define PAD 136                          // bf16 elems per row (272B); rows rotate banks by 4
#define TILE_BYTES (128 * PAD * 2)       // 34816 per tile
#define SA_HI  0
#define SA_LO  (TILE_BYTES)
#define SW1_HI (2 * TILE_BYTES)
#define SW1_LO (3 * TILE_BYTES)
#define SW2_HI (4 * TILE_BYTES)
#define SW2_LO (5 * TILE_BYTES)
#define SM_TOTAL (6 * TILE_BYTES)        // 208896 B

__device__ __forceinline__ float lrelu(float x) { return x > 0.f ? x : 0.01f * x; }
__device__ __forceinline__ unsigned pack2(float a, float b) {
    unsigned short ua = __bfloat16_as_ushort(__float2bfloat16_rn(a));
    unsigned short ub = __bfloat16_as_ushort(__float2bfloat16_rn(b));
    return (unsigned)ua | ((unsigned)ub << 16);
}
__device__ __forceinline__ float bflo(float x) {
    return x - __bfloat162float(__float2bfloat16_rn(x));
}

__device__ __forceinline__ uint32_t smem_u32(const void* p) {
    uint32_t a;
    asm("{ .reg .u64 t; cvta.to.shared.u64 t, %1; cvt.u32.u64 %0, t; }" : "=r"(a) : "l"(p));
    return a;
}

__device__ __forceinline__ void mma16816(float* c, const unsigned* a, const unsigned* b) {
    asm volatile(
        "mma.sync.aligned.m16n8k16.row.col.f32.bf16.bf16.f32 "
        "{%0,%1,%2,%3}, {%4,%5,%6,%7}, {%8,%9}, {%0,%1,%2,%3};"
        : "+f"(c[0]), "+f"(c[1]), "+f"(c[2]), "+f"(c[3])
        : "r"(a[0]), "r"(a[1]), "r"(a[2]), "r"(a[3]), "r"(b[0]), "r"(b[1]));
}

__device__ __forceinline__ void ldsm4(unsigned* r, uint32_t addr) {
    asm volatile("ldmatrix.sync.aligned.m8n8.x4.shared.b16 {%0,%1,%2,%3}, [%4];"
                 : "=r"(r[0]), "=r"(r[1]), "=r"(r[2]), "=r"(r[3]) : "r"(addr));
}

__device__ __forceinline__ void st_pairs(char* smem, int base, int r, int k,
                                         float x0, float x1, float x2, float x3,
                                         int lo_base) {
    unsigned* hp = (unsigned*)(smem + base + r * (PAD * 2) + k * 2);
    hp[0] = pack2(x0, x1);
    hp[1] = pack2(x2, x3);
    unsigned* lp = (unsigned*)(smem + lo_base + r * (PAD * 2) + k * 2);
    lp[0] = pack2(bflo(x0), bflo(x1));
    lp[1] = pack2(bflo(x2), bflo(x3));
}

__global__ void __launch_bounds__(256, 1)
mma_gemm_kernel(const float* __restrict__ nfeat,
                const float* __restrict__ W1,
                const float* __restrict__ W2,
                const float* __restrict__ hn,
                float* __restrict__ out) {
    extern __shared__ char smem[];
    uint32_t sb = smem_u32(smem);
    int tid  = threadIdx.x;
    int wid  = tid >> 5;
    int lane = tid & 31;
    int g8   = lane >> 2;        // 0..7
    int t4   = lane & 3;         // 0..3

    int warp_r = wid >> 2;       // 0..1  -> row base warp_r*64
    int warp_c = wid & 3;        // 0..3  -> col base warp_c*32

    // ---- per-lane ldmatrix address components (bytes) ----
    int a_off = (warp_r * 64 + ((lane >> 3) & 1) * 8 + (lane & 7)) * (PAD * 2)
              + (lane >> 4) * 8 * 2;
    int b_off0 = (warp_c * 32 + (0 + (lane >> 4)) * 8 + (lane & 7)) * (PAD * 2)
               + ((lane >> 3) & 1) * 8 * 2;
    int b_off1 = (warp_c * 32 + (2 + (lane >> 4)) * 8 + (lane & 7)) * (PAD * 2)
               + ((lane >> 3) & 1) * 8 * 2;

    // ---- stage weight splits once ----
    {
        int r  = tid >> 1;           // 0..127 (output col)
        int kc = (tid & 1) * 64;
        const float4* w1p = (const float4*)(W1 + (size_t)r * D + kc);
        const float4* w2p = (const float4*)(W2 + (size_t)r * D + kc);
        #pragma unroll
        for (int i = 0; i < 16; i++) {
            float4 a = __ldg(w1p + i);
            float4 b = __ldg(w2p + i);
            int k = kc + i * 4;
            st_pairs(smem, SW1_HI, r, k, a.x, a.y, a.z, a.w, SW1_LO);
            st_pairs(smem, SW2_HI, r, k, b.x, b.y, b.z, b.w, SW2_LO);
        }
    }
    __syncthreads();

    const int n_tiles = (N_NODES + 127) / 128;   // 391

    for (int tile = blockIdx.x; tile < n_tiles; tile += gridDim.x) {
        int n0 = tile * 128;

        float acc[2][4][4][4];   // [branch][mi][ni][frag]
        #pragma unroll
        for (int b = 0; b < 2; b++)
            #pragma unroll
            for (int mi = 0; mi < 4; mi++)
                #pragma unroll
                for (int ni = 0; ni < 4; ni++)
                    #pragma unroll
                    for (int f = 0; f < 4; f++) acc[b][mi][ni][f] = 0.f;

        #pragma unroll
        for (int branch = 0; branch < 2; branch++) {
            // ---- stage A (h+hn or h*hn) hi/lo ----
            {
                int r  = tid >> 1;
                int kc = (tid & 1) * 64;
                int g  = n0 + r;
                const float4* hp = (const float4*)(nfeat + (size_t)g * D + kc);
                const float4* np = (const float4*)(hn    + (size_t)g * D + kc);
                #pragma unroll
                for (int i = 0; i < 16; i++) {
                    float4 v = make_float4(0.f, 0.f, 0.f, 0.f);
                    if (g < N_NODES) {
                        float4 hv = __ldg(hp + i);
                        float4 nv = __ldg(np + i);
                        v = (branch == 0)
                          ? make_float4(hv.x + nv.x, hv.y + nv.y, hv.z + nv.z, hv.w + nv.w)
                          : make_float4(hv.x * nv.x, hv.y * nv.y, hv.z * nv.z, hv.w * nv.w);
                    }
                    st_pairs(smem, SA_HI, r, kc + i * 4, v.x, v.y, v.z, v.w, SA_LO);
                }
            }
            __syncthreads();

            uint32_t bhi_base = sb + ((branch == 0) ? SW1_HI : SW2_HI);
            uint32_t blo_base = sb + ((branch == 0) ? SW1_LO : SW2_LO);
            float*   accb     = &acc[branch][0][0][0];

            // ---- pass 1: aHi x (bHi + bLo) ----
            #pragma unroll
            for (int kk = 0; kk < 8; kk++) {
                int kb2 = kk * 32;              // kb*2 bytes
                unsigned afr[4][4];
                #pragma unroll
                for (int mi = 0; mi < 4; mi++)
                    ldsm4(afr[mi], sb + SA_HI + a_off + mi * 16 * (PAD * 2) + kb2);
                unsigned bh[8], bl[8];
                ldsm4(bh,     bhi_base + b_off0 + kb2);
                ldsm4(bh + 4, bhi_base + b_off1 + kb2);
                ldsm4(bl,     blo_base + b_off0 + kb2);
                ldsm4(bl + 4, blo_base + b_off1 + kb2);
                #pragma unroll
                for (int mi = 0; mi < 4; mi++)
                    #pragma unroll
                    for (int ni = 0; ni < 4; ni++) {
                        float* c = accb + (mi * 4 + ni) * 4;
                        mma16816(c, afr[mi], bh + ni * 2);
                        mma16816(c, afr[mi], bl + ni * 2);
                    }
            }

            // ---- pass 2: aLo x bHi ----
            #pragma unroll
            for (int kk = 0; kk < 8; kk++) {
                int kb2 = kk * 32;
                unsigned afr[4][4];
                #pragma unroll
                for (int mi = 0; mi < 4; mi++)
                    ldsm4(afr[mi], sb + SA_LO + a_off + mi * 16 * (PAD * 2) + kb2);
                unsigned bh[8];
                ldsm4(bh,     bhi_base + b_off0 + kb2);
                ldsm4(bh + 4, bhi_base + b_off1 + kb2);
                #pragma unroll
                for (int mi = 0; mi < 4; mi++)
                    #pragma unroll
                    for (int ni = 0; ni < 4; ni++)
                        mma16816(accb + (mi * 4 + ni) * 4, afr[mi], bh + ni * 2);
            }
            __syncthreads();   // done reading A before next branch restages
        }

        // ---- epilogue: lrelu(add) + lrelu(mul), write fp32 ----
        #pragma unroll
        for (int mi = 0; mi < 4; mi++) {
            int r_lo = n0 + warp_r * 64 + mi * 16 + g8;
            int r_hi = r_lo + 8;
            #pragma unroll
            for (int ni = 0; ni < 4; ni++) {
                int c0 = warp_c * 32 + ni * 8 + t4 * 2;
                if (r_lo < N_NODES) {
                    float2 o;
                    o.x = lrelu(acc[0][mi][ni][0]) + lrelu(acc[1][mi][ni][0]);
                    o.y = lrelu(acc[0][mi][ni][1]) + lrelu(acc[1][mi][ni][1]);
                    *(float2*)(out + (size_t)r_lo * D + c0) = o;
                }
                if (r_hi < N_NODES) {
                    float2 o;
                    o.x = lrelu(acc[0][mi][ni][2]) + lrelu(acc[1][mi][ni][2]);
                    o.y = lrelu(acc[0][mi][ni][3]) + lrelu(acc[1][mi][ni][3]);
                    *(float2*)(out + (size_t)r_hi * D + c0) = o;
                }
            }
        }
    }
}

// ---------------- launch ----------------
extern "C" void kernel_launch(void* const* d_in, const int* in_sizes, int n_in,
                              void* d_out, int out_size) {
    const float* nfeat = (const float*)d_in[0];
    const float* w     = (const float*)d_in[1];
    const float* W1    = (const float*)d_in[2];
    const float* W2    = (const float*)d_in[3];
    const void*  src   = d_in[4];
    const void*  dst   = d_in[5];

    float* outbuf = (float*)d_out;
    float* hn     = outbuf;                           // h_neighbor
    float* out2   = outbuf + (size_t)N_NODES * D;     // out

    zero_detect_kernel<<<(N_NODES + 255) / 256, 256>>>(src, dst);
    count_kernel<<<(N_EDGES + 255) / 256, 256>>>(dst);
    scan_lookback_kernel<<<SCAN_NBLK, 256>>>();
    scatter_kernel<<<(N_EDGES + 255) / 256, 256>>>(src, dst, w);
    aggregate_kernel<<<(N_NODES * 32 + 255) / 256, 256>>>(nfeat, hn);

    cudaFuncSetAttribute(mma_gemm_kernel,
                         cudaFuncAttributeMaxDynamicSharedMemorySize, SM_TOTAL);
    mma_gemm_kernel<<<148, 256, SM_TOTAL>>>(nfeat, W1, W2, hn, out2);
}

// round 10
// speedup vs baseline: 2.2926x; 1.1379x over previous
#include <cuda_runtime.h>
#include <cuda_bf16.h>
#include <cstdint>

#define N_NODES 50000
#define N_EDGES 640000
#define D 128

#define SCAN_TILE 1024
#define SCAN_NBLK ((N_NODES + SCAN_TILE - 1) / SCAN_TILE)   // 49

typedef unsigned long long ULL;

// ---------------- device scratch (no allocations allowed) ----------------
__device__ int                g_is64;
__device__ int                g_count[N_NODES];
__device__ int                g_offsets[N_NODES + 1];
__device__ int                g_cursor[N_NODES];
__device__ unsigned int       g_scanstate[SCAN_NBLK];
__device__ ULL                g_edge_sorted[N_EDGES];   // (w_bits<<32) | src

__device__ __forceinline__ int edge_idx(const void* p, int i, int is64) {
    if (is64) return (int)__ldg(((const long long*)p) + i);
    return __ldg(((const int*)p) + i);
}

// ---------------- init ----------------
__global__ void zero_detect_kernel(const void* src, const void* dst) {
    int i = blockIdx.x * blockDim.x + threadIdx.x;
    if (i < N_NODES) g_count[i] = 0;
    if (i < SCAN_NBLK) g_scanstate[i] = 0u;
    if (i == 0) {
        g_offsets[N_NODES] = N_EDGES;
        const long long* s = (const long long*)src;
        const long long* d = (const long long*)dst;
        bool ok = true;
        for (int j = 0; j < 8; j++) {
            long long a = s[j], b = d[j];
            if (a < 0 || a >= N_NODES || b < 0 || b >= N_NODES) { ok = false; break; }
        }
        g_is64 = ok ? 1 : 0;
    }
}

__global__ void count_kernel(const void* dst) {
    int e = blockIdx.x * blockDim.x + threadIdx.x;
    if (e >= N_EDGES) return;
    int is64 = g_is64;
    atomicAdd(&g_count[edge_idx(dst, e, is64)], 1);
}

// ---------------- single-pass exclusive scan, decoupled lookback ----------------
__global__ void scan_lookback_kernel() {
    __shared__ int warpsums[8];
    __shared__ int blockexcl;
    int t    = threadIdx.x;
    int lane = t & 31;
    int wrp  = t >> 5;
    int b    = blockIdx.x;
    int base = b * SCAN_TILE + t * 4;

    int c[4];
    int lsum = 0;
    #pragma unroll
    for (int i = 0; i < 4; i++) {
        int idx = base + i;
        c[i] = (idx < N_NODES) ? g_count[idx] : 0;
        lsum += c[i];
    }
    int incl = lsum;
    #pragma unroll
    for (int o = 1; o < 32; o <<= 1) {
        int v = __shfl_up_sync(0xFFFFFFFF, incl, o);
        if (lane >= o) incl += v;
    }
    if (lane == 31) warpsums[wrp] = incl;
    __syncthreads();

    if (t == 0) {
        int tot = 0;
        #pragma unroll
        for (int wv = 0; wv < 8; wv++) tot += warpsums[wv];
        atomicExch(&g_scanstate[b], 0x80000000u | (unsigned)tot);
    }
    if (wrp == 0) {
        int psum = 0;
        for (int p = lane; p < b; p += 32) {
            unsigned v;
            do { v = atomicOr(&g_scanstate[p], 0u); } while (!(v & 0x80000000u));
            psum += (int)(v & 0x7FFFFFFFu);
        }
        #pragma unroll
        for (int o = 16; o > 0; o >>= 1) psum += __shfl_down_sync(0xFFFFFFFF, psum, o);
        if (lane == 0) blockexcl = psum;
    }
    __syncthreads();

    int wbase = 0;
    #pragma unroll
    for (int wv = 0; wv < 8; wv++) {
        int v = warpsums[wv];
        if (wv < wrp) wbase += v;
    }
    int run = blockexcl + wbase + (incl - lsum);
    #pragma unroll
    for (int i = 0; i < 4; i++) {
        int idx = base + i;
        if (idx < N_NODES) {
            g_offsets[idx] = run;
            g_cursor[idx]  = run;
            run += c[i];
        }
    }
}

__global__ void scatter_kernel(const void* src, const void* dst, const float* __restrict__ w) {
    int e = blockIdx.x * blockDim.x + threadIdx.x;
    if (e >= N_EDGES) return;
    int is64 = g_is64;
    int d = edge_idx(dst, e, is64);
    int s = edge_idx(src, e, is64);
    float wv = __ldg(w + e);
    int pos = atomicAdd(&g_cursor[d], 1);
    g_edge_sorted[pos] = ((ULL)__float_as_uint(wv) << 32) | (unsigned)s;
}

// ---------------- per-node aggregation: one warp per node ----------------
__global__ void aggregate_kernel(const float* __restrict__ nfeat, float* __restrict__ hn) {
    int gwarp = (blockIdx.x * blockDim.x + threadIdx.x) >> 5;
    int lane  = threadIdx.x & 31;
    if (gwarp >= N_NODES) return;
    int beg = g_offsets[gwarp];
    int end = g_offsets[gwarp + 1];
    float4 acc = make_float4(0.f, 0.f, 0.f, 0.f);
    int e = beg;
    for (; e + 3 < end; e += 4) {
        ULL p0 = __ldg(&g_edge_sorted[e]);
        ULL p1 = __ldg(&g_edge_sorted[e + 1]);
        ULL p2 = __ldg(&g_edge_sorted[e + 2]);
        ULL p3 = __ldg(&g_edge_sorted[e + 3]);
        float4 v0 = __ldg(((const float4*)(nfeat + (size_t)(unsigned)(p0 & 0xFFFFFFFFu) * D)) + lane);
        float4 v1 = __ldg(((const float4*)(nfeat + (size_t)(unsigned)(p1 & 0xFFFFFFFFu) * D)) + lane);
        float4 v2 = __ldg(((const float4*)(nfeat + (size_t)(unsigned)(p2 & 0xFFFFFFFFu) * D)) + lane);
        float4 v3 = __ldg(((const float4*)(nfeat + (size_t)(unsigned)(p3 & 0xFFFFFFFFu) * D)) + lane);
        float w0 = __uint_as_float((unsigned)(p0 >> 32));
        float w1 = __uint_as_float((unsigned)(p1 >> 32));
        float w2 = __uint_as_float((unsigned)(p2 >> 32));
        float w3 = __uint_as_float((unsigned)(p3 >> 32));
        acc.x += w0 * v0.x; acc.y += w0 * v0.y; acc.z += w0 * v0.z; acc.w += w0 * v0.w;
        acc.x += w1 * v1.x; acc.y += w1 * v1.y; acc.z += w1 * v1.z; acc.w += w1 * v1.w;
        acc.x += w2 * v2.x; acc.y += w2 * v2.y; acc.z += w2 * v2.z; acc.w += w2 * v2.w;
        acc.x += w3 * v3.x; acc.y += w3 * v3.y; acc.z += w3 * v3.z; acc.w += w3 * v3.w;
    }
    for (; e < end; e++) {
        ULL p0 = __ldg(&g_edge_sorted[e]);
        float4 v0 = __ldg(((const float4*)(nfeat + (size_t)(unsigned)(p0 & 0xFFFFFFFFu) * D)) + lane);
        float w0 = __uint_as_float((unsigned)(p0 >> 32));
        acc.x += w0 * v0.x; acc.y += w0 * v0.y; acc.z += w0 * v0.z; acc.w += w0 * v0.w;
    }
    ((float4*)(hn + (size_t)gwarp * D))[lane] = acc;
}

// ================= mma.sync bi-interaction GEMM, M=64 tiles =================
// out = lrelu((h+hn) @ W1^T) + lrelu((h*hn) @ W2^T)
// bf16 split: hi = bit-truncated fp32 (exact bf16), lo = rn(v - hi).
// Products kept: AhiBhi + AhiBlo + AloBhi; residual ~2^-16.
// Stage BOTH branch A-matrices once per tile -> 2 syncthreads/tile.

#define PAD 136                          // bf16 elems per row (272B)
#define WTILE_B (128 * PAD * 2)          // 34816
#define ATILE_B (64 * PAD * 2)           // 17408
#define SW1_HI 0
#define SW1_LO (SW1_HI + WTILE_B)
#define SW2_HI (SW1_LO + WTILE_B)
#define SW2_LO (SW2_HI + WTILE_B)
#define SADD_HI (SW2_LO + WTILE_B)
#define SADD_LO (SADD_HI + ATILE_B)
#define SMUL_HI (SADD_LO + ATILE_B)
#define SMUL_LO (SMUL_HI + ATILE_B)
#define SM_TOTAL (SMUL_LO + ATILE_B)     // 208896 B

__device__ __forceinline__ float lrelu(float x) { return x > 0.f ? x : 0.01f * x; }
__device__ __forceinline__ unsigned pack2(float a, float b) {
    unsigned short ua = __bfloat16_as_ushort(__float2bfloat16_rn(a));
    unsigned short ub = __bfloat16_as_ushort(__float2bfloat16_rn(b));
    return (unsigned)ua | ((unsigned)ub << 16);
}
__device__ __forceinline__ float bflo(float x) {
    return x - __bfloat162float(__float2bfloat16_rn(x));
}
__device__ __forceinline__ uint32_t smem_u32(const void* p) {
    uint32_t a;
    asm("{ .reg .u64 t; cvta.to.shared.u64 t, %1; cvt.u32.u64 %0, t; }" : "=r"(a) : "l"(p));
    return a;
}
__device__ __forceinline__ void mma16816(float* c, const unsigned* a, const unsigned* b) {
    asm volatile(
        "mma.sync.aligned.m16n8k16.row.col.f32.bf16.bf16.f32 "
        "{%0,%1,%2,%3}, {%4,%5,%6,%7}, {%8,%9}, {%0,%1,%2,%3};"
        : "+f"(c[0]), "+f"(c[1]), "+f"(c[2]), "+f"(c[3])
        : "r"(a[0]), "r"(a[1]), "r"(a[2]), "r"(a[3]), "r"(b[0]), "r"(b[1]));
}
__device__ __forceinline__ void ldsm4(unsigned* r, uint32_t addr) {
    asm volatile("ldmatrix.sync.aligned.m8n8.x4.shared.b16 {%0,%1,%2,%3}, [%4];"
                 : "=r"(r[0]), "=r"(r[1]), "=r"(r[2]), "=r"(r[3]) : "r"(addr));
}

// W staging: round-nearest hi/lo (one-time cost)
__device__ __forceinline__ void st_pairs(char* smem, int base, int r, int k,
                                         float x0, float x1, float x2, float x3,
                                         int lo_base) {
    unsigned* hp = (unsigned*)(smem + base + r * (PAD * 2) + k * 2);
    hp[0] = pack2(x0, x1);
    hp[1] = pack2(x2, x3);
    unsigned* lp = (unsigned*)(smem + lo_base + r * (PAD * 2) + k * 2);
    lp[0] = pack2(bflo(x0), bflo(x1));
    lp[1] = pack2(bflo(x2), bflo(x3));
}

// A staging: truncation hi (LOP+PRMT) + rn lo (FSUB + bf16x2 cvt) — ~3 ops/value
__device__ __forceinline__ void stA(char* smem, int hbase, int lbase, int r, int k, float4 v) {
    unsigned u0 = __float_as_uint(v.x), u1 = __float_as_uint(v.y);
    unsigned u2 = __float_as_uint(v.z), u3 = __float_as_uint(v.w);
    unsigned h0, h1;
    asm("prmt.b32 %0, %1, %2, 0x7632;" : "=r"(h0) : "r"(u0), "r"(u1));
    asm("prmt.b32 %0, %1, %2, 0x7632;" : "=r"(h1) : "r"(u2), "r"(u3));
    float l0 = v.x - __uint_as_float(u0 & 0xffff0000u);
    float l1 = v.y - __uint_as_float(u1 & 0xffff0000u);
    float l2 = v.z - __uint_as_float(u2 & 0xffff0000u);
    float l3 = v.w - __uint_as_float(u3 & 0xffff0000u);
    unsigned p0, p1;
    asm("cvt.rn.bf16x2.f32 %0, %1, %2;" : "=r"(p0) : "f"(l1), "f"(l0));  // low half = l0
    asm("cvt.rn.bf16x2.f32 %0, %1, %2;" : "=r"(p1) : "f"(l3), "f"(l2));
    *(uint2*)(smem + hbase + r * (PAD * 2) + k * 2) = make_uint2(h0, h1);
    *(uint2*)(smem + lbase + r * (PAD * 2) + k * 2) = make_uint2(p0, p1);
}

__global__ void __launch_bounds__(256, 1)
mma_gemm_kernel(const float* __restrict__ nfeat,
                const float* __restrict__ W1,
                const float* __restrict__ W2,
                const float* __restrict__ hn,
                float* __restrict__ out) {
    extern __shared__ char smem[];
    uint32_t sb = smem_u32(smem);
    int tid  = threadIdx.x;
    int wid  = tid >> 5;
    int lane = tid & 31;
    int g8   = lane >> 2;
    int t4   = lane & 3;

    int warp_r = wid >> 2;       // 0..1 -> row base warp_r*32
    int warp_c = wid & 3;        // 0..3 -> col base warp_c*32

    // ldmatrix per-lane offsets (bytes)
    int a_off = (warp_r * 32 + ((lane >> 3) & 1) * 8 + (lane & 7)) * (PAD * 2)
              + (lane >> 4) * 16;
    int b_off0 = (warp_c * 32 + (0 + (lane >> 4)) * 8 + (lane & 7)) * (PAD * 2)
               + ((lane >> 3) & 1) * 16;
    int b_off1 = (warp_c * 32 + (2 + (lane >> 4)) * 8 + (lane & 7)) * (PAD * 2)
               + ((lane >> 3) & 1) * 16;

    // stage weight splits once
    {
        int r  = tid >> 1;
        int kc = (tid & 1) * 64;
        const float4* w1p = (const float4*)(W1 + (size_t)r * D + kc);
        const float4* w2p = (const float4*)(W2 + (size_t)r * D + kc);
        #pragma unroll
        for (int i = 0; i < 16; i++) {
            float4 a = __ldg(w1p + i);
            float4 b = __ldg(w2p + i);
            int k = kc + i * 4;
            st_pairs(smem, SW1_HI, r, k, a.x, a.y, a.z, a.w, SW1_LO);
            st_pairs(smem, SW2_HI, r, k, b.x, b.y, b.z, b.w, SW2_LO);
        }
    }
    __syncthreads();

    const int n_tiles = (N_NODES + 63) / 64;   // 782

    for (int tile = blockIdx.x; tile < n_tiles; tile += gridDim.x) {
        int n0 = tile * 64;

        // ---- stage BOTH branches once: thread t -> row t>>2, col quarter t&3 ----
        {
            int r  = tid >> 2;               // 0..63
            int c0 = (tid & 3) * 32;         // 0,32,64,96
            int g  = n0 + r;
            const float4* hp = (const float4*)(nfeat + (size_t)g * D + c0);
            const float4* np = (const float4*)(hn    + (size_t)g * D + c0);
            #pragma unroll
            for (int i = 0; i < 8; i++) {
                float4 av = make_float4(0.f, 0.f, 0.f, 0.f);
                float4 mv = av;
                if (g < N_NODES) {
                    float4 hv = __ldg(hp + i);
                    float4 nv = __ldg(np + i);
                    av = make_float4(hv.x + nv.x, hv.y + nv.y, hv.z + nv.z, hv.w + nv.w);
                    mv = make_float4(hv.x * nv.x, hv.y * nv.y, hv.z * nv.z, hv.w * nv.w);
                }
                int k = c0 + i * 4;
                stA(smem, SADD_HI, SADD_LO, r, k, av);
                stA(smem, SMUL_HI, SMUL_LO, r, k, mv);
            }
        }
        __syncthreads();

        float acc[2][2][4][4];
        #pragma unroll
        for (int b = 0; b < 2; b++)
            #pragma unroll
            for (int mi = 0; mi < 2; mi++)
                #pragma unroll
                for (int ni = 0; ni < 4; ni++)
                    #pragma unroll
                    for (int f = 0; f < 4; f++) acc[b][mi][ni][f] = 0.f;

        #pragma unroll
        for (int branch = 0; branch < 2; branch++) {
            uint32_t ahi = sb + (branch ? SMUL_HI : SADD_HI);
            uint32_t alo = sb + (branch ? SMUL_LO : SADD_LO);
            uint32_t bhi = sb + (branch ? SW2_HI : SW1_HI);
            uint32_t blo = sb + (branch ? SW2_LO : SW1_LO);
            float*   accb = &acc[branch][0][0][0];

            // pass 1: aHi x (bHi + bLo)
            #pragma unroll
            for (int kk = 0; kk < 8; kk++) {
                int kb2 = kk * 32;
                unsigned afr[2][4];
                ldsm4(afr[0], ahi + a_off + kb2);
                ldsm4(afr[1], ahi + a_off + 16 * (PAD * 2) + kb2);
                unsigned bh[8], bl[8];
                ldsm4(bh,     bhi + b_off0 + kb2);
                ldsm4(bh + 4, bhi + b_off1 + kb2);
                ldsm4(bl,     blo + b_off0 + kb2);
                ldsm4(bl + 4, blo + b_off1 + kb2);
                #pragma unroll
                for (int mi = 0; mi < 2; mi++)
                    #pragma unroll
                    for (int ni = 0; ni < 4; ni++) {
                        float* c = accb + (mi * 4 + ni) * 4;
                        mma16816(c, afr[mi], bh + ni * 2);
                        mma16816(c, afr[mi], bl + ni * 2);
                    }
            }
            // pass 2: aLo x bHi
            #pragma unroll
            for (int kk = 0; kk < 8; kk++) {
                int kb2 = kk * 32;
                unsigned afr[2][4];
                ldsm4(afr[0], alo + a_off + kb2);
                ldsm4(afr[1], alo + a_off + 16 * (PAD * 2) + kb2);
                unsigned bh[8];
                ldsm4(bh,     bhi + b_off0 + kb2);
                ldsm4(bh + 4, bhi + b_off1 + kb2);
                #pragma unroll
                for (int mi = 0; mi < 2; mi++)
                    #pragma unroll
                    for (int ni = 0; ni < 4; ni++)
                        mma16816(accb + (mi * 4 + ni) * 4, afr[mi], bh + ni * 2);
            }
        }

        // ---- epilogue ----
        #pragma unroll
        for (int mi = 0; mi < 2; mi++) {
            int r_lo = n0 + warp_r * 32 + mi * 16 + g8;
            int r_hi = r_lo + 8;
            #pragma unroll
            for (int ni = 0; ni < 4; ni++) {
                int c0 = warp_c * 32 + ni * 8 + t4 * 2;
                if (r_lo < N_NODES) {
                    float2 o;
                    o.x = lrelu(acc[0][mi][ni][0]) + lrelu(acc[1][mi][ni][0]);
                    o.y = lrelu(acc[0][mi][ni][1]) + lrelu(acc[1][mi][ni][1]);
                    *(float2*)(out + (size_t)r_lo * D + c0) = o;
                }
                if (r_hi < N_NODES) {
                    float2 o;
                    o.x = lrelu(acc[0][mi][ni][2]) + lrelu(acc[1][mi][ni][2]);
                    o.y = lrelu(acc[0][mi][ni][3]) + lrelu(acc[1][mi][ni][3]);
                    *(float2*)(out + (size_t)r_hi * D + c0) = o;
                }
            }
        }
        __syncthreads();   // A buffers reusable next tile
    }
}

// ---------------- launch ----------------
extern "C" void kernel_launch(void* const* d_in, const int* in_sizes, int n_in,
                              void* d_out, int out_size) {
    const float* nfeat = (const float*)d_in[0];
    const float* w     = (const float*)d_in[1];
    const float* W1    = (const float*)d_in[2];
    const float* W2    = (const float*)d_in[3];
    const void*  src   = d_in[4];
    const void*  dst   = d_in[5];

    float* outbuf = (float*)d_out;
    float* hn     = outbuf;                           // h_neighbor
    float* out2   = outbuf + (size_t)N_NODES * D;     // out

    zero_detect_kernel<<<(N_NODES + 255) / 256, 256>>>(src, dst);
    count_kernel<<<(N_EDGES + 255) / 256, 256>>>(dst);
    scan_lookback_kernel<<<SCAN_NBLK, 256>>>();
    scatter_kernel<<<(N_EDGES + 255) / 256, 256>>>(src, dst, w);
    aggregate_kernel<<<(N_NODES * 32 + 255) / 256, 256>>>(nfeat, hn);

    cudaFuncSetAttribute(mma_gemm_kernel,
                         cudaFuncAttributeMaxDynamicSharedMemorySize, SM_TOTAL);
    mma_gemm_kernel<<<148, 256, SM_TOTAL>>>(nfeat, W1, W2, hn, out2);
}